// round 14
// baseline (speedup 1.0000x reference)
#include <cuda_runtime.h>
#include <cuda_bf16.h>
#include <cstdint>

#define BB   4
#define NTOK 4096
#define CC   256
#define NHH  8
#define HDD  32
#define LL   9
#define PP   64
#define TT   4096

// ---------------- scratch ----------------
__device__ float g_big  [BB*NTOK*1024];    // [q | k | v | xs]
__device__ float g_qs   [BB*NTOK*CC];
__device__ float g_kn   [BB*NTOK*CC];
__device__ float g_pln  [BB*PP*CC];
__device__ float g_cpb  [TT*NHH];
__device__ float g_alt  [BB*NTOK*NHH*12];
__device__ float g_S    [BB*NHH*NTOK*PP];  // pool logits (+bias)

// bf16 operands
__device__ __nv_bfloat16 g_xh [BB*NTOK*CC], g_xl [BB*NTOK*CC];
__device__ __nv_bfloat16 g_ath[BB*NTOK*CC], g_atl[BB*NTOK*CC];
__device__ __nv_bfloat16 g_wbh[1024*CC],    g_wbl[1024*CC];
__device__ __nv_bfloat16 g_pwh[CC*CC],      g_pwl[CC*CC];
__device__ float         g_bigb[1024];
__device__ __nv_bfloat16 g_qshh[BB*NHH*NTOK*HDD], g_qshl[BB*NHH*NTOK*HDD];
__device__ __nv_bfloat16 g_kph [BB*NHH*PP*HDD],   g_kpl [BB*NHH*PP*HDD];
__device__ __nv_bfloat16 g_vth [BB*NHH*HDD*PP],   g_vtl [BB*NHH*HDD*PP];

// ---------------- helpers ----------------
__device__ __forceinline__ uint32_t smem_u32(const void* p) {
    uint32_t a;
    asm("{ .reg .u64 t; cvta.to.shared.u64 t, %1; cvt.u32.u64 %0, t; }" : "=r"(a) : "l"(p));
    return a;
}
__device__ __forceinline__ void cp_async16(uint32_t dst, const void* src) {
    asm volatile("cp.async.cg.shared.global [%0], [%1], 16;" :: "r"(dst), "l"(src) : "memory");
}
#define CP_COMMIT() asm volatile("cp.async.commit_group;" ::: "memory")
#define CP_WAIT0()  asm volatile("cp.async.wait_group 0;" ::: "memory")

__device__ __forceinline__ void ldmx4(uint32_t* r, uint32_t addr) {
    asm volatile("ldmatrix.sync.aligned.m8n8.x4.shared.b16 {%0,%1,%2,%3}, [%4];"
                 : "=r"(r[0]), "=r"(r[1]), "=r"(r[2]), "=r"(r[3]) : "r"(addr));
}
__device__ __forceinline__ void mma16816(float* c, const uint32_t* a, uint32_t b0, uint32_t b1) {
    asm volatile("mma.sync.aligned.m16n8k16.row.col.f32.bf16.bf16.f32 "
                 "{%0,%1,%2,%3}, {%4,%5,%6,%7}, {%8,%9}, {%0,%1,%2,%3};"
                 : "+f"(c[0]), "+f"(c[1]), "+f"(c[2]), "+f"(c[3])
                 : "r"(a[0]), "r"(a[1]), "r"(a[2]), "r"(a[3]), "r"(b0), "r"(b1));
}
__device__ __forceinline__ uint32_t pack_bf2(float a, float b) {
    __nv_bfloat162 t = __floats2bfloat162_rn(a, b);
    return *(uint32_t*)&t;
}

// ---------------- x hi/lo split ----------------
__global__ void cvt_hilo(const float* __restrict__ src,
                         __nv_bfloat16* __restrict__ hi,
                         __nv_bfloat16* __restrict__ lo, int n)
{
    int i = blockIdx.x * 256 + threadIdx.x;
    if (i < n) {
        float v = src[i];
        __nv_bfloat16 h = __float2bfloat16(v);
        hi[i] = h;
        lo[i] = __float2bfloat16(v - __bfloat162float(h));
    }
}

// ---------------- fused weight conversion ----------------
#define NW (1024*CC)
#define NPJ (CC*CC)
__global__ void cvt_weights(const float* __restrict__ qw, const float* __restrict__ kvw,
                            const float* __restrict__ srw, const float* __restrict__ pjw,
                            const float* __restrict__ qb, const float* __restrict__ kvb,
                            const float* __restrict__ srb)
{
    int idx = blockIdx.x * 256 + threadIdx.x;
    if (idx < NW) {
        int row = idx >> 8, col = idx & 255;
        float v = (row < 256) ? qw[row*256 + col]
                : (row < 768) ? kvw[(row-256)*256 + col]
                              : srw[(row-768)*256 + col];
        __nv_bfloat16 h = __float2bfloat16(v);
        g_wbh[idx] = h;
        g_wbl[idx] = __float2bfloat16(v - __bfloat162float(h));
    } else if (idx < NW + NPJ) {
        int j = idx - NW;
        float v = pjw[j];
        __nv_bfloat16 h = __float2bfloat16(v);
        g_pwh[j] = h;
        g_pwl[j] = __float2bfloat16(v - __bfloat162float(h));
    } else if (idx < NW + NPJ + 1024) {
        int j = idx - NW - NPJ;
        g_bigb[j] = (j < 256) ? qb[j] : (j < 768) ? kvb[j-256] : srb[j-768];
    }
}

// ---------------- HMMA GEMM (proven) ----------------
#define GS_A0   0
#define GS_A1   16384
#define GS_W0   32768
#define GS_W1   49152
#define GS_BIAS 65536
#define GS_TOT  66048

__global__ __launch_bounds__(256) void gemm_mma(
    const __nv_bfloat16* __restrict__ Ah, const __nv_bfloat16* __restrict__ Al,
    const __nv_bfloat16* __restrict__ Wh, const __nv_bfloat16* __restrict__ Wl,
    const float* __restrict__ bias, float* __restrict__ Y, int Nout, int act)
{
    extern __shared__ __align__(128) char smem[];
    const uint32_t sb = smem_u32(smem);
    float* sbias = (float*)(smem + GS_BIAS);

    const int tid = threadIdx.x, wid = tid >> 5, lane = tid & 31;
    const int n0 = blockIdx.x * 128, m0 = blockIdx.y * 128;
    const int warp_m = wid & 1, warp_n = wid >> 1;
    const bool do_gelu = (act == 1) || (act == 2 && n0 >= 768);

    if (tid < 128) sbias[tid] = bias[n0 + tid];

    float acc[4][4][4];
    #pragma unroll
    for (int i = 0; i < 4; i++)
        #pragma unroll
        for (int j = 0; j < 4; j++)
            #pragma unroll
            for (int e = 0; e < 4; e++) acc[i][j][e] = 0.f;

    const int lrow0 = tid >> 3;
    const int luc   = tid & 7;

    auto issue = [&](int c, int buf) {
        int seg = c >> 2, ks0 = (c & 3) * 64;
        const __nv_bfloat16* Asrc = (seg < 2) ? Ah : Al;
        const __nv_bfloat16* Wsrc = (seg == 1) ? Wl : Wh;
        uint32_t ab = sb + (buf ? GS_A1 : GS_A0);
        uint32_t wb = sb + (buf ? GS_W1 : GS_W0);
        #pragma unroll
        for (int i = 0; i < 4; i++) {
            int row = lrow0 + i * 32;
            uint32_t soff = (uint32_t)row * 128 + (uint32_t)((luc ^ (row & 7)) * 16);
            cp_async16(ab + soff, Asrc + (size_t)(m0 + row) * CC + ks0 + luc * 8);
            cp_async16(wb + soff, Wsrc + (size_t)(n0 + row) * CC + ks0 + luc * 8);
        }
        CP_COMMIT();
    };

    issue(0, 0);

    for (int c = 0; c < 12; c++) {
        CP_WAIT0();
        __syncthreads();
        if (c + 1 < 12) issue(c + 1, (c + 1) & 1);

        const uint32_t ab = sb + ((c & 1) ? GS_A1 : GS_A0);
        const uint32_t wb = sb + ((c & 1) ? GS_W1 : GS_W0);

        #pragma unroll
        for (int ks = 0; ks < 4; ks++) {
            uint32_t afr[4][4];
            #pragma unroll
            for (int tm = 0; tm < 4; tm++) {
                int row = warp_m * 64 + tm * 16 + (lane & 15);
                int cc  = ks * 2 + (lane >> 4);
                ldmx4(afr[tm], ab + (uint32_t)row * 128 + (uint32_t)((cc ^ (row & 7)) * 16));
            }
            uint32_t bfr[2][4];
            #pragma unroll
            for (int tp = 0; tp < 2; tp++) {
                int g = lane >> 3;
                int row = warp_n * 32 + tp * 16 + ((g >> 1) & 1) * 8 + (lane & 7);
                int cc  = ks * 2 + (g & 1);
                ldmx4(bfr[tp], wb + (uint32_t)row * 128 + (uint32_t)((cc ^ (row & 7)) * 16));
            }
            #pragma unroll
            for (int tm = 0; tm < 4; tm++)
                #pragma unroll
                for (int tn = 0; tn < 4; tn++)
                    mma16816(acc[tm][tn], afr[tm],
                             bfr[tn >> 1][(tn & 1) * 2], bfr[tn >> 1][(tn & 1) * 2 + 1]);
        }
    }

    #pragma unroll
    for (int tm = 0; tm < 4; tm++) {
        int gr = m0 + warp_m * 64 + tm * 16 + (lane >> 2);
        #pragma unroll
        for (int tn = 0; tn < 4; tn++) {
            int lc = warp_n * 32 + tn * 8 + 2 * (lane & 3);
            int gc = n0 + lc;
            float b0 = sbias[lc], b1 = sbias[lc + 1];
            float r0 = acc[tm][tn][0] + b0, r1 = acc[tm][tn][1] + b1;
            float r2 = acc[tm][tn][2] + b0, r3 = acc[tm][tn][3] + b1;
            if (do_gelu) {
                r0 *= normcdff(r0); r1 *= normcdff(r1);
                r2 *= normcdff(r2); r3 *= normcdff(r3);
            }
            *(float2*)&Y[(size_t)gr * Nout + gc]       = make_float2(r0, r1);
            *(float2*)&Y[(size_t)(gr + 8) * Nout + gc] = make_float2(r2, r3);
        }
    }
}

// ---------------- normalize (softplus hoisted to smem) ----------------
__global__ void normalize_kernel(const float* __restrict__ qe,
                                 const float* __restrict__ temp,
                                 const float* __restrict__ sls)
{
    __shared__ float sp[NHH];
    int bn = blockIdx.x;
    int n  = bn & (NTOK - 1);
    int b  = bn >> 12;
    int c  = threadIdx.x;
    int h  = c >> 5, d = c & 31;

    if (c < NHH) sp[c] = log1pf(expf(temp[c]));

    float yq = g_big[(size_t)bn*1024 + c];
    float yk = g_big[(size_t)bn*1024 + 256 + c];

    float sq = yq*yq;
    #pragma unroll
    for (int o = 16; o; o >>= 1) sq += __shfl_xor_sync(0xffffffffu, sq, o);
    float qn = yq / fmaxf(sqrtf(sq), 1e-12f);

    float sk = yk*yk;
    #pragma unroll
    for (int o = 16; o; o >>= 1) sk += __shfl_xor_sync(0xffffffffu, sk, o);
    float kn = yk / fmaxf(sqrtf(sk), 1e-12f);

    __syncthreads();
    float qs = (qn + qe[c]) * (sp[h] * sls[n]);

    g_qs[bn*CC + c] = qs;
    g_kn[bn*CC + c] = kn;

    size_t hm = ((size_t)(b*NHH + h)*NTOK + n)*HDD + d;
    __nv_bfloat16 qh = __float2bfloat16(qs);
    g_qshh[hm] = qh;
    g_qshl[hm] = __float2bfloat16(qs - __bfloat162float(qh));
}

// ---------------- learnable-token precompute (from qs) ----------------
__global__ void alt_kernel(const float* __restrict__ lt_g, const float* __restrict__ lb_g,
                           const float* __restrict__ qe, const float* __restrict__ temp,
                           const float* __restrict__ sls)
{
    __shared__ float lts[NHH*HDD*LL];
    __shared__ float lbs[NHH*LL];
    __shared__ float qelt[NHH*LL];
    __shared__ float sp[NHH];
    int tid = threadIdx.x;
    for (int i = tid; i < NHH*HDD*LL; i += 256) lts[i] = lt_g[i];
    if (tid < NHH*LL) lbs[tid] = lb_g[tid];
    if (tid < NHH) sp[tid] = log1pf(expf(temp[tid]));
    __syncthreads();
    if (tid < NHH*LL) {
        int h = tid / LL, l = tid % LL;
        float s = 0.f;
        for (int d = 0; d < HDD; d++)
            s += qe[h*HDD + d] * lts[(h*HDD + d)*LL + l];
        qelt[tid] = s;
    }
    __syncthreads();

    int idx = blockIdx.x * 256 + tid;
    int bn = idx >> 3, h = idx & 7, n = bn & (NTOK - 1);

    const float* qrow = g_qs + (size_t)bn * CC + h * HDD;
    float invs = 1.f / (sp[h] * sls[n]);
    float acc[LL];
    #pragma unroll
    for (int l = 0; l < LL; l++) acc[l] = 0.f;
    #pragma unroll 4
    for (int d = 0; d < HDD; d++) {
        float q = qrow[d];
        #pragma unroll
        for (int l = 0; l < LL; l++)
            acc[l] = fmaf(q, lts[(h*HDD + d)*LL + l], acc[l]);
    }
    float* outp = g_alt + (size_t)idx * 12;
    #pragma unroll
    for (int l = 0; l < LL; l++)
        outp[l] = acc[l] * invs - qelt[h*LL + l] + lbs[h*LL + l];
    outp[9] = 0.f; outp[10] = 0.f; outp[11] = 0.f;
}

// ---------------- 8x8 avg pool + layernorm ----------------
__global__ void pool_ln_kernel(const float* __restrict__ ng,
                               const float* __restrict__ nb)
{
    int bp = blockIdx.x;
    int b  = bp >> 6, p = bp & 63;
    int ph = p >> 3, pw = p & 7;
    int c  = threadIdx.x;

    float s = 0.f;
    for (int r = 0; r < 8; r++)
        #pragma unroll
        for (int q = 0; q < 8; q++) {
            int n = (ph*8 + r) * 64 + pw*8 + q;
            s += g_big[(size_t)(b*NTOK + n)*1024 + 768 + c];
        }
    float avg = s * (1.f/64.f);

    float v1 = avg, v2 = avg*avg;
    #pragma unroll
    for (int o = 16; o; o >>= 1) {
        v1 += __shfl_xor_sync(0xffffffffu, v1, o);
        v2 += __shfl_xor_sync(0xffffffffu, v2, o);
    }
    __shared__ float s1[8], s2[8];
    int w = c >> 5, lane = c & 31;
    if (lane == 0) { s1[w] = v1; s2[w] = v2; }
    __syncthreads();
    float m1 = 0.f, m2 = 0.f;
    #pragma unroll
    for (int ww = 0; ww < 8; ww++) { m1 += s1[ww]; m2 += s2[ww]; }
    m1 *= (1.f/256.f); m2 *= (1.f/256.f);
    float var = m2 - m1*m1;
    g_pln[bp*CC + c] = (avg - m1) * rsqrtf(var + 1e-5f) * ng[c] + nb[c];
}

// ---------------- pooled kv projection -> bf16 splits ----------------
__global__ void kvpool_kernel(const float* __restrict__ kv_w,
                              const float* __restrict__ kv_b)
{
    int bp = blockIdx.x; int b = bp >> 6, p = bp & 63;
    __shared__ __align__(16) float xr[CC];
    int tid = threadIdx.x;
    if (tid < CC) xr[tid] = g_pln[bp*CC + tid];
    __syncthreads();

    int o = tid;
    float acc = kv_b[o];
    const float4* w4 = (const float4*)(kv_w + (size_t)o * CC);
    const float4* x4 = (const float4*)xr;
    #pragma unroll 8
    for (int k = 0; k < 64; k++) {
        float4 w = w4[k], xv = x4[k];
        acc += w.x*xv.x + w.y*xv.y + w.z*xv.z + w.w*xv.w;
    }
    int lane = tid & 31;
    if (o < CC) {
        float s = acc*acc;
        #pragma unroll
        for (int q = 16; q; q >>= 1) s += __shfl_xor_sync(0xffffffffu, s, q);
        float kn = acc / fmaxf(sqrtf(s), 1e-12f);
        int h = o >> 5;
        size_t idx = ((size_t)(b*NHH + h)*PP + p)*HDD + lane;
        __nv_bfloat16 kh = __float2bfloat16(kn);
        g_kph[idx] = kh;
        g_kpl[idx] = __float2bfloat16(kn - __bfloat162float(kh));
    } else {
        int oo = o - CC; int h = oo >> 5, d = oo & 31;
        size_t idx = ((size_t)(b*NHH + h)*HDD + d)*PP + p;
        __nv_bfloat16 vh = __float2bfloat16(acc);
        g_vth[idx] = vh;
        g_vtl[idx] = __float2bfloat16(acc - __bfloat162float(vh));
    }
}

// ---------------- CPB MLP ----------------
__global__ void cpb_kernel(const float* __restrict__ table,
                           const float* __restrict__ w1, const float* __restrict__ b1,
                           const float* __restrict__ w2, const float* __restrict__ b2)
{
    __shared__ float sw1[1024], sb1[512], sw2[4096];
    int tid = threadIdx.x;
    for (int i = tid; i < 1024; i += 128) sw1[i] = w1[i];
    for (int i = tid; i <  512; i += 128) sb1[i] = b1[i];
    for (int i = tid; i < 4096; i += 128) sw2[i] = w2[i];
    __syncthreads();

    int t = blockIdx.x * 128 + tid;
    float c0 = table[2*t], c1 = table[2*t+1];
    float acc[NHH];
    #pragma unroll
    for (int h = 0; h < NHH; h++) acc[h] = b2[h];
    for (int j = 0; j < 512; j++) {
        float hj = fmaxf(fmaf(c0, sw1[2*j], fmaf(c1, sw1[2*j+1], sb1[j])), 0.f);
        #pragma unroll
        for (int h = 0; h < NHH; h++) acc[h] = fmaf(hj, sw2[h*512 + j], acc[h]);
    }
    #pragma unroll
    for (int h = 0; h < NHH; h++) g_cpb[t*NHH + h] = acc[h];
}

// ---------------- pool logits mma (bias gathered inline from cpb via rpi) ----------------
__global__ __launch_bounds__(128) void pool_logits_mma(const int* __restrict__ rpi)
{
    __shared__ __align__(128) char smem[24576];
    const uint32_t sb = smem_u32(smem);
    const int tid = threadIdx.x, w = tid >> 5, lane = tid & 31;
    const int bh = blockIdx.y, m0 = blockIdx.x * 128;
    const int h = bh & 7;
    const uint32_t A0 = 0, A1 = 8192, B0 = 16384, B1 = 20480;

    #pragma unroll
    for (int it = 0; it < 4; it++) {
        int idx = it*128 + tid, row = idx >> 2, ch = idx & 3;
        uint32_t so = (uint32_t)row*64 + (uint32_t)((ch ^ (row & 3))*16);
        const size_t src = ((size_t)bh*NTOK + m0 + row)*HDD + ch*8;
        cp_async16(sb + A0 + so, g_qshh + src);
        cp_async16(sb + A1 + so, g_qshl + src);
    }
    #pragma unroll
    for (int it = 0; it < 2; it++) {
        int idx = it*128 + tid, row = idx >> 2, ch = idx & 3;
        uint32_t so = (uint32_t)row*64 + (uint32_t)((ch ^ (row & 3))*16);
        const size_t src = ((size_t)bh*PP + row)*HDD + ch*8;
        cp_async16(sb + B0 + so, g_kph + src);
        cp_async16(sb + B1 + so, g_kpl + src);
    }
    CP_COMMIT(); CP_WAIT0();
    __syncthreads();

    float acc[2][8][4];
    #pragma unroll
    for (int i = 0; i < 2; i++)
        #pragma unroll
        for (int j = 0; j < 8; j++)
            #pragma unroll
            for (int e = 0; e < 4; e++) acc[i][j][e] = 0.f;

    #pragma unroll
    for (int pass = 0; pass < 3; pass++) {
        const uint32_t ab = sb + ((pass == 2) ? A1 : A0);
        const uint32_t bb = sb + ((pass == 1) ? B1 : B0);
        #pragma unroll
        for (int ks = 0; ks < 2; ks++) {
            uint32_t afr[2][4];
            #pragma unroll
            for (int tm = 0; tm < 2; tm++) {
                int row = w*32 + tm*16 + (lane & 15);
                int cc  = ks*2 + (lane >> 4);
                ldmx4(afr[tm], ab + (uint32_t)row*64 + (uint32_t)((cc ^ (row & 3))*16));
            }
            uint32_t bfr[4][4];
            #pragma unroll
            for (int tp = 0; tp < 4; tp++) {
                int g = lane >> 3;
                int row = tp*16 + ((g >> 1) & 1)*8 + (lane & 7);
                int cc  = ks*2 + (g & 1);
                ldmx4(bfr[tp], bb + (uint32_t)row*64 + (uint32_t)((cc ^ (row & 3))*16));
            }
            #pragma unroll
            for (int tm = 0; tm < 2; tm++)
                #pragma unroll
                for (int tn = 0; tn < 8; tn++)
                    mma16816(acc[tm][tn], afr[tm],
                             bfr[tn >> 1][(tn & 1)*2], bfr[tn >> 1][(tn & 1)*2 + 1]);
        }
    }

    #pragma unroll
    for (int tm = 0; tm < 2; tm++) {
        int gn = m0 + w*32 + tm*16 + (lane >> 2);
        #pragma unroll
        for (int tn = 0; tn < 8; tn++) {
            int p = tn*8 + 2*(lane & 3);
            int2 r0 = *(const int2*)&rpi[gn*PP + p];
            int2 r1 = *(const int2*)&rpi[(gn+8)*PP + p];
            float pb00 = g_cpb[r0.x*NHH + h], pb01 = g_cpb[r0.y*NHH + h];
            float pb10 = g_cpb[r1.x*NHH + h], pb11 = g_cpb[r1.y*NHH + h];
            *(float2*)&g_S[((size_t)bh*NTOK + gn)*PP + p] =
                make_float2(acc[tm][tn][0] + pb00, acc[tm][tn][1] + pb01);
            *(float2*)&g_S[((size_t)bh*NTOK + gn + 8)*PP + p] =
                make_float2(acc[tm][tn][2] + pb10, acc[tm][tn][3] + pb11);
        }
    }
}

// ---------------- attn7: softmax + pool-output mma fused ----------------
#define AT_A0 0
#define AT_A1 16384
#define AT_B0 32768
#define AT_B1 36864
#define AT_XL 40960
#define AT_TOT 57344

__global__ __launch_bounds__(128) void attn_kernel7(const float* __restrict__ rpb_g)
{
    __shared__ __align__(128) char smem[AT_TOT];
    const uint32_t sb = smem_u32(smem);
    float* xl = (float*)(smem + AT_XL);

    const int tid = threadIdx.x;
    const int bh = blockIdx.y, b = bh >> 3, h = bh & 7, m0 = blockIdx.x * 128;
    const int w = tid >> 5, lane = tid & 31;
    const int tsub = lane >> 3, dg = lane & 7;

    #pragma unroll
    for (int it = 0; it < 2; it++) {
        int idx = it*128 + tid, row = idx >> 3, ch = idx & 7;
        uint32_t so = (uint32_t)row*128 + (uint32_t)((ch ^ (row & 7))*16);
        const size_t src = ((size_t)bh*HDD + row)*PP + ch*8;
        cp_async16(sb + AT_B0 + so, g_vth + src);
        cp_async16(sb + AT_B1 + so, g_vtl + src);
    }
    CP_COMMIT();

    float rpbl[LL];
    #pragma unroll
    for (int l = 0; l < LL; l++) rpbl[l] = rpb_g[h*LL + l];

    for (int s = 0; s < 8; s++) {
        const int n = m0 + w*32 + s*4 + tsub;
        const int i = n >> 6, j = n & 63;
        const int r = n - m0;

        float4 qv = *(const float4*)(g_qs + (size_t)(b*NTOK + n)*CC + h*HDD + dg*4);

        float el[LL];
        bool  vlm[LL];
        #pragma unroll
        for (int l = 0; l < LL; l++) {
            int ii = i + l/3 - 1, jj = j + l%3 - 1;
            vlm[l] = ((unsigned)ii < 64u) && ((unsigned)jj < 64u);
            float sv = 0.f;
            if (vlm[l]) {
                float4 k4 = *(const float4*)(g_kn +
                    (size_t)(b*NTOK + ii*64 + jj)*CC + h*HDD + dg*4);
                sv = qv.x*k4.x + qv.y*k4.y + qv.z*k4.z + qv.w*k4.w;
            }
            el[l] = sv;
        }
        #pragma unroll
        for (int l = 0; l < LL; l++) {
            float sv = el[l];
            sv += __shfl_xor_sync(0xffffffffu, sv, 1);
            sv += __shfl_xor_sync(0xffffffffu, sv, 2);
            sv += __shfl_xor_sync(0xffffffffu, sv, 4);
            el[l] = vlm[l] ? (sv + rpbl[l]) : -1e30f;
        }

        const float* Sp = g_S + ((size_t)bh*NTOK + n)*PP + dg*8;
        float4 s03 = *(const float4*)Sp;
        float4 s47 = *(const float4*)(Sp + 4);
        float pl[8] = { s03.x, s03.y, s03.z, s03.w, s47.x, s47.y, s47.z, s47.w };

        float m = el[0];
        #pragma unroll
        for (int l = 1; l < LL; l++) m = fmaxf(m, el[l]);
        #pragma unroll
        for (int p = 0; p < 8; p++) m = fmaxf(m, pl[p]);
        m = fmaxf(m, __shfl_xor_sync(0xffffffffu, m, 1));
        m = fmaxf(m, __shfl_xor_sync(0xffffffffu, m, 2));
        m = fmaxf(m, __shfl_xor_sync(0xffffffffu, m, 4));

        float els = 0.f;
        #pragma unroll
        for (int l = 0; l < LL; l++) { el[l] = __expf(el[l] - m); els += el[l]; }
        float pes = 0.f;
        #pragma unroll
        for (int p = 0; p < 8; p++) { pl[p] = __expf(pl[p] - m); pes += pl[p]; }
        pes += __shfl_xor_sync(0xffffffffu, pes, 1);
        pes += __shfl_xor_sync(0xffffffffu, pes, 2);
        pes += __shfl_xor_sync(0xffffffffu, pes, 4);
        float inv = 1.f / (pes + els);

        {
            float wv[8], lv[8];
            #pragma unroll
            for (int p = 0; p < 8; p++) {
                wv[p] = pl[p] * inv;
                float hi = __bfloat162float(__float2bfloat16(wv[p]));
                lv[p] = wv[p] - hi;
            }
            uint4 uh, ul;
            uh.x = pack_bf2(wv[0], wv[1]); uh.y = pack_bf2(wv[2], wv[3]);
            uh.z = pack_bf2(wv[4], wv[5]); uh.w = pack_bf2(wv[6], wv[7]);
            ul.x = pack_bf2(lv[0], lv[1]); ul.y = pack_bf2(lv[2], lv[3]);
            ul.z = pack_bf2(lv[4], lv[5]); ul.w = pack_bf2(lv[6], lv[7]);
            uint32_t so = (uint32_t)r*128 + (uint32_t)((dg ^ (r & 7))*16);
            *(uint4*)(smem + AT_A0 + so) = uh;
            *(uint4*)(smem + AT_A1 + so) = ul;
        }

        const float* altp = g_alt + ((size_t)(b*NTOK + n)*NHH + h)*12;
        float4 a03 = *(const float4*)altp;
        float4 a47 = *(const float4*)(altp + 4);
        float  a8  = altp[8];
        float av[LL] = { a03.x, a03.y, a03.z, a03.w, a47.x, a47.y, a47.z, a47.w, a8 };
        #pragma unroll
        for (int l = 0; l < LL; l++) av[l] += el[l]*inv;

        float4 xo = make_float4(0.f, 0.f, 0.f, 0.f);
        #pragma unroll
        for (int l = 0; l < LL; l++) {
            if (vlm[l]) {
                int ii = i + l/3 - 1, jj = j + l%3 - 1;
                float4 v4 = *(const float4*)(g_big +
                    (size_t)(b*NTOK + ii*64 + jj)*1024 + 512 + h*HDD + dg*4);
                xo.x = fmaf(av[l], v4.x, xo.x);
                xo.y = fmaf(av[l], v4.y, xo.y);
                xo.z = fmaf(av[l], v4.z, xo.z);
                xo.w = fmaf(av[l], v4.w, xo.w);
            }
        }
        *(float4*)(xl + r*32 + dg*4) = xo;
    }

    CP_WAIT0();
    __syncthreads();

    float acc[2][4][4];
    #pragma unroll
    for (int i = 0; i < 2; i++)
        #pragma unroll
        for (int j = 0; j < 4; j++)
            #pragma unroll
            for (int e = 0; e < 4; e++) acc[i][j][e] = 0.f;

    #pragma unroll
    for (int pass = 0; pass < 3; pass++) {
        const uint32_t ab = sb + ((pass == 2) ? AT_A1 : AT_A0);
        const uint32_t bb = sb + ((pass == 1) ? AT_B1 : AT_B0);
        #pragma unroll
        for (int ks = 0; ks < 4; ks++) {
            uint32_t afr[2][4];
            #pragma unroll
            for (int tm = 0; tm < 2; tm++) {
                int row = w*32 + tm*16 + (lane & 15);
                int cc  = ks*2 + (lane >> 4);
                ldmx4(afr[tm], ab + (uint32_t)row*128 + (uint32_t)((cc ^ (row & 7))*16));
            }
            uint32_t bfr[2][4];
            #pragma unroll
            for (int tp = 0; tp < 2; tp++) {
                int g = lane >> 3;
                int row = tp*16 + ((g >> 1) & 1)*8 + (lane & 7);
                int cc  = ks*2 + (g & 1);
                ldmx4(bfr[tp], bb + (uint32_t)row*128 + (uint32_t)((cc ^ (row & 7))*16));
            }
            #pragma unroll
            for (int tm = 0; tm < 2; tm++)
                #pragma unroll
                for (int tn = 0; tn < 4; tn++)
                    mma16816(acc[tm][tn], afr[tm],
                             bfr[tn >> 1][(tn & 1)*2], bfr[tn >> 1][(tn & 1)*2 + 1]);
        }
    }

    #pragma unroll
    for (int tm = 0; tm < 2; tm++) {
        #pragma unroll
        for (int half = 0; half < 2; half++) {
            int r = w*32 + tm*16 + (lane >> 2) + half*8;
            int gn = m0 + r;
            #pragma unroll
            for (int tn = 0; tn < 4; tn++) {
                int d = tn*8 + 2*(lane & 3);
                float2 x2 = *(const float2*)&xl[r*32 + d];
                float r0 = acc[tm][tn][half*2 + 0] + x2.x;
                float r1 = acc[tm][tn][half*2 + 1] + x2.y;
                __nv_bfloat16 h0 = __float2bfloat16(r0), h1 = __float2bfloat16(r1);
                size_t off = (size_t)(b*NTOK + gn)*CC + h*HDD + d;
                *(uint32_t*)(g_ath + off) = pack_bf2(r0, r1);
                *(uint32_t*)(g_atl + off) = pack_bf2(r0 - __bfloat162float(h0),
                                                     r1 - __bfloat162float(h1));
            }
        }
    }
}

// ---------------- launch ----------------
extern "C" void kernel_launch(void* const* d_in, const int* in_sizes, int n_in,
                              void* d_out, int out_size)
{
    const float* x      = (const float*)d_in[0];
    const int*   rpi    = (const int*)  d_in[1];
    const float* table  = (const float*)d_in[2];
    const float* q_w    = (const float*)d_in[3];
    const float* q_b    = (const float*)d_in[4];
    const float* kv_w   = (const float*)d_in[5];
    const float* kv_b   = (const float*)d_in[6];
    const float* temp   = (const float*)d_in[7];
    const float* qe     = (const float*)d_in[8];
    const float* proj_w = (const float*)d_in[9];
    const float* proj_b = (const float*)d_in[10];
    const float* sr_w   = (const float*)d_in[11];
    const float* sr_b   = (const float*)d_in[12];
    const float* norm_g = (const float*)d_in[13];
    const float* norm_b = (const float*)d_in[14];
    const float* cpb1_w = (const float*)d_in[15];
    const float* cpb1_b = (const float*)d_in[16];
    const float* cpb2_w = (const float*)d_in[17];
    const float* cpb2_b = (const float*)d_in[18];
    const float* rpb    = (const float*)d_in[19];
    const float* lt     = (const float*)d_in[20];
    const float* lb     = (const float*)d_in[21];
    const float* sls    = (const float*)d_in[22];
    float* out = (float*)d_out;

    void *p_big, *p_xh, *p_xl, *p_ath, *p_atl, *p_wbh, *p_wbl, *p_pwh, *p_pwl, *p_bigb;
    cudaGetSymbolAddress(&p_big,  g_big);
    cudaGetSymbolAddress(&p_xh,   g_xh);  cudaGetSymbolAddress(&p_xl,  g_xl);
    cudaGetSymbolAddress(&p_ath,  g_ath); cudaGetSymbolAddress(&p_atl, g_atl);
    cudaGetSymbolAddress(&p_wbh,  g_wbh); cudaGetSymbolAddress(&p_wbl, g_wbl);
    cudaGetSymbolAddress(&p_pwh,  g_pwh); cudaGetSymbolAddress(&p_pwl, g_pwl);
    cudaGetSymbolAddress(&p_bigb, g_bigb);

    const int M = BB * NTOK;
    const int NX = M * CC;

    cudaFuncSetAttribute(gemm_mma, cudaFuncAttributeMaxDynamicSharedMemorySize, GS_TOT);

    #define BF(p) ((__nv_bfloat16*)(p))
    // launch 1-3: cvts + cpb (independent); launch 4 = big GEMM (ncu capture slot)
    cvt_hilo<<<(NX+255)/256, 256>>>(x, BF(p_xh), BF(p_xl), NX);
    cvt_weights<<<(NW + NPJ + 1024 + 255)/256, 256>>>(q_w, kv_w, sr_w, proj_w,
                                                      q_b, kv_b, sr_b);
    cpb_kernel<<<TT/128, 128>>>(table, cpb1_w, cpb1_b, cpb2_w, cpb2_b);
    gemm_mma<<<dim3(8, M/128), 256, GS_TOT>>>(BF(p_xh), BF(p_xl), BF(p_wbh), BF(p_wbl),
                                              (float*)p_bigb, (float*)p_big, 1024, 2);

    normalize_kernel<<<M, CC>>>(qe, temp, sls);
    pool_ln_kernel<<<BB*PP, CC>>>(norm_g, norm_b);
    kvpool_kernel<<<BB*PP, 512>>>(kv_w, kv_b);
    alt_kernel<<<(M*NHH)/256, 256>>>(lt, lb, qe, temp, sls);

    pool_logits_mma<<<dim3(NTOK/128, BB*NHH), 128>>>(rpi);
    attn_kernel7<<<dim3(NTOK/128, BB*NHH), 128>>>(rpb);

    gemm_mma<<<dim3(2, M/128), 256, GS_TOT>>>(BF(p_ath), BF(p_atl), BF(p_pwh), BF(p_pwl),
                                              proj_b, out, CC, 0);
    #undef BF
}

// round 15
// speedup vs baseline: 1.0298x; 1.0298x over previous
#include <cuda_runtime.h>
#include <cuda_bf16.h>
#include <cstdint>

#define BB   4
#define NTOK 4096
#define CC   256
#define NHH  8
#define HDD  32
#define LL   9
#define PP   64
#define TT   4096

// ---------------- scratch ----------------
__device__ float g_big  [BB*NTOK*1024];    // [q | k | v | xs]
__device__ float g_kn   [BB*NTOK*CC];
__device__ float g_pln  [BB*PP*CC];
__device__ float g_cpb  [TT*NHH];
__device__ float g_pb   [NTOK*NHH*PP];     // [n][h][p]
__device__ float g_alt  [BB*NTOK*NHH*12];
__device__ float g_S    [BB*NHH*NTOK*PP];  // pool logits (+bias)
__device__ float g_xloc [BB*NHH*NTOK*HDD]; // local-path output

// bf16 operands
__device__ __nv_bfloat16 g_xh [BB*NTOK*CC], g_xl [BB*NTOK*CC];
__device__ __nv_bfloat16 g_ath[BB*NTOK*CC], g_atl[BB*NTOK*CC];
__device__ __nv_bfloat16 g_wbh[1024*CC],    g_wbl[1024*CC];
__device__ __nv_bfloat16 g_pwh[CC*CC],      g_pwl[CC*CC];
__device__ float         g_bigb[1024];
__device__ __nv_bfloat16 g_qshh[BB*NHH*NTOK*HDD], g_qshl[BB*NHH*NTOK*HDD]; // [bh][n][d]
__device__ __nv_bfloat16 g_kph [BB*NHH*PP*HDD],   g_kpl [BB*NHH*PP*HDD];
__device__ __nv_bfloat16 g_vth [BB*NHH*HDD*PP],   g_vtl [BB*NHH*HDD*PP];
__device__ __nv_bfloat16 g_apwh[BB*NHH*NTOK*PP],  g_apwl[BB*NHH*NTOK*PP];

// ---------------- helpers ----------------
__device__ __forceinline__ uint32_t smem_u32(const void* p) {
    uint32_t a;
    asm("{ .reg .u64 t; cvta.to.shared.u64 t, %1; cvt.u32.u64 %0, t; }" : "=r"(a) : "l"(p));
    return a;
}
__device__ __forceinline__ void cp_async16(uint32_t dst, const void* src) {
    asm volatile("cp.async.cg.shared.global [%0], [%1], 16;" :: "r"(dst), "l"(src) : "memory");
}
#define CP_COMMIT() asm volatile("cp.async.commit_group;" ::: "memory")
#define CP_WAIT0()  asm volatile("cp.async.wait_group 0;" ::: "memory")

__device__ __forceinline__ void ldmx4(uint32_t* r, uint32_t addr) {
    asm volatile("ldmatrix.sync.aligned.m8n8.x4.shared.b16 {%0,%1,%2,%3}, [%4];"
                 : "=r"(r[0]), "=r"(r[1]), "=r"(r[2]), "=r"(r[3]) : "r"(addr));
}
__device__ __forceinline__ void mma16816(float* c, const uint32_t* a, uint32_t b0, uint32_t b1) {
    asm volatile("mma.sync.aligned.m16n8k16.row.col.f32.bf16.bf16.f32 "
                 "{%0,%1,%2,%3}, {%4,%5,%6,%7}, {%8,%9}, {%0,%1,%2,%3};"
                 : "+f"(c[0]), "+f"(c[1]), "+f"(c[2]), "+f"(c[3])
                 : "r"(a[0]), "r"(a[1]), "r"(a[2]), "r"(a[3]), "r"(b0), "r"(b1));
}
__device__ __forceinline__ uint32_t pack_bf2(float a, float b) {
    __nv_bfloat162 t = __floats2bfloat162_rn(a, b);
    return *(uint32_t*)&t;
}
__device__ __forceinline__ float2 bf2f(uint32_t u) {
    __nv_bfloat162 t = *(__nv_bfloat162*)&u;
    return make_float2(__bfloat162float(t.x), __bfloat162float(t.y));
}

// ---------------- x hi/lo split ----------------
__global__ void cvt_hilo(const float* __restrict__ src,
                         __nv_bfloat16* __restrict__ hi,
                         __nv_bfloat16* __restrict__ lo, int n)
{
    int i = blockIdx.x * 256 + threadIdx.x;
    if (i < n) {
        float v = src[i];
        __nv_bfloat16 h = __float2bfloat16(v);
        hi[i] = h;
        lo[i] = __float2bfloat16(v - __bfloat162float(h));
    }
}

// ---------------- fused weight conversion ----------------
#define NW (1024*CC)
#define NPJ (CC*CC)
__global__ void cvt_weights(const float* __restrict__ qw, const float* __restrict__ kvw,
                            const float* __restrict__ srw, const float* __restrict__ pjw,
                            const float* __restrict__ qb, const float* __restrict__ kvb,
                            const float* __restrict__ srb)
{
    int idx = blockIdx.x * 256 + threadIdx.x;
    if (idx < NW) {
        int row = idx >> 8, col = idx & 255;
        float v = (row < 256) ? qw[row*256 + col]
                : (row < 768) ? kvw[(row-256)*256 + col]
                              : srw[(row-768)*256 + col];
        __nv_bfloat16 h = __float2bfloat16(v);
        g_wbh[idx] = h;
        g_wbl[idx] = __float2bfloat16(v - __bfloat162float(h));
    } else if (idx < NW + NPJ) {
        int j = idx - NW;
        float v = pjw[j];
        __nv_bfloat16 h = __float2bfloat16(v);
        g_pwh[j] = h;
        g_pwl[j] = __float2bfloat16(v - __bfloat162float(h));
    } else if (idx < NW + NPJ + 1024) {
        int j = idx - NW - NPJ;
        g_bigb[j] = (j < 256) ? qb[j] : (j < 768) ? kvb[j-256] : srb[j-768];
    }
}

// ---------------- HMMA GEMM (proven) ----------------
#define GS_A0   0
#define GS_A1   16384
#define GS_W0   32768
#define GS_W1   49152
#define GS_BIAS 65536
#define GS_TOT  66048

__global__ __launch_bounds__(256) void gemm_mma(
    const __nv_bfloat16* __restrict__ Ah, const __nv_bfloat16* __restrict__ Al,
    const __nv_bfloat16* __restrict__ Wh, const __nv_bfloat16* __restrict__ Wl,
    const float* __restrict__ bias, float* __restrict__ Y, int Nout, int act)
{
    extern __shared__ __align__(128) char smem[];
    const uint32_t sb = smem_u32(smem);
    float* sbias = (float*)(smem + GS_BIAS);

    const int tid = threadIdx.x, wid = tid >> 5, lane = tid & 31;
    const int n0 = blockIdx.x * 128, m0 = blockIdx.y * 128;
    const int warp_m = wid & 1, warp_n = wid >> 1;
    const bool do_gelu = (act == 1) || (act == 2 && n0 >= 768);

    if (tid < 128) sbias[tid] = bias[n0 + tid];

    float acc[4][4][4];
    #pragma unroll
    for (int i = 0; i < 4; i++)
        #pragma unroll
        for (int j = 0; j < 4; j++)
            #pragma unroll
            for (int e = 0; e < 4; e++) acc[i][j][e] = 0.f;

    const int lrow0 = tid >> 3;
    const int luc   = tid & 7;

    auto issue = [&](int c, int buf) {
        int seg = c >> 2, ks0 = (c & 3) * 64;
        const __nv_bfloat16* Asrc = (seg < 2) ? Ah : Al;
        const __nv_bfloat16* Wsrc = (seg == 1) ? Wl : Wh;
        uint32_t ab = sb + (buf ? GS_A1 : GS_A0);
        uint32_t wb = sb + (buf ? GS_W1 : GS_W0);
        #pragma unroll
        for (int i = 0; i < 4; i++) {
            int row = lrow0 + i * 32;
            uint32_t soff = (uint32_t)row * 128 + (uint32_t)((luc ^ (row & 7)) * 16);
            cp_async16(ab + soff, Asrc + (size_t)(m0 + row) * CC + ks0 + luc * 8);
            cp_async16(wb + soff, Wsrc + (size_t)(n0 + row) * CC + ks0 + luc * 8);
        }
        CP_COMMIT();
    };

    issue(0, 0);

    for (int c = 0; c < 12; c++) {
        CP_WAIT0();
        __syncthreads();
        if (c + 1 < 12) issue(c + 1, (c + 1) & 1);

        const uint32_t ab = sb + ((c & 1) ? GS_A1 : GS_A0);
        const uint32_t wb = sb + ((c & 1) ? GS_W1 : GS_W0);

        #pragma unroll
        for (int ks = 0; ks < 4; ks++) {
            uint32_t afr[4][4];
            #pragma unroll
            for (int tm = 0; tm < 4; tm++) {
                int row = warp_m * 64 + tm * 16 + (lane & 15);
                int cc  = ks * 2 + (lane >> 4);
                ldmx4(afr[tm], ab + (uint32_t)row * 128 + (uint32_t)((cc ^ (row & 7)) * 16));
            }
            uint32_t bfr[2][4];
            #pragma unroll
            for (int tp = 0; tp < 2; tp++) {
                int g = lane >> 3;
                int row = warp_n * 32 + tp * 16 + ((g >> 1) & 1) * 8 + (lane & 7);
                int cc  = ks * 2 + (g & 1);
                ldmx4(bfr[tp], wb + (uint32_t)row * 128 + (uint32_t)((cc ^ (row & 7)) * 16));
            }
            #pragma unroll
            for (int tm = 0; tm < 4; tm++)
                #pragma unroll
                for (int tn = 0; tn < 4; tn++)
                    mma16816(acc[tm][tn], afr[tm],
                             bfr[tn >> 1][(tn & 1) * 2], bfr[tn >> 1][(tn & 1) * 2 + 1]);
        }
    }

    #pragma unroll
    for (int tm = 0; tm < 4; tm++) {
        int gr = m0 + warp_m * 64 + tm * 16 + (lane >> 2);
        #pragma unroll
        for (int tn = 0; tn < 4; tn++) {
            int lc = warp_n * 32 + tn * 8 + 2 * (lane & 3);
            int gc = n0 + lc;
            float b0 = sbias[lc], b1 = sbias[lc + 1];
            float r0 = acc[tm][tn][0] + b0, r1 = acc[tm][tn][1] + b1;
            float r2 = acc[tm][tn][2] + b0, r3 = acc[tm][tn][3] + b1;
            if (do_gelu) {
                r0 *= normcdff(r0); r1 *= normcdff(r1);
                r2 *= normcdff(r2); r3 *= normcdff(r3);
            }
            *(float2*)&Y[(size_t)gr * Nout + gc]       = make_float2(r0, r1);
            *(float2*)&Y[(size_t)(gr + 8) * Nout + gc] = make_float2(r2, r3);
        }
    }
}

// ---------------- normalize: kn fp32 + qs bf16 hi/lo head-major (no fp32 qs) ----------------
__global__ void normalize_kernel(const float* __restrict__ qe,
                                 const float* __restrict__ temp,
                                 const float* __restrict__ sls)
{
    int bn = blockIdx.x;
    int n  = bn & (NTOK - 1);
    int b  = bn >> 12;
    int c  = threadIdx.x;
    int h  = c >> 5, d = c & 31;

    float yq = g_big[(size_t)bn*1024 + c];
    float yk = g_big[(size_t)bn*1024 + 256 + c];

    float sq = yq*yq;
    #pragma unroll
    for (int o = 16; o; o >>= 1) sq += __shfl_xor_sync(0xffffffffu, sq, o);
    float qn = yq / fmaxf(sqrtf(sq), 1e-12f);

    float sk = yk*yk;
    #pragma unroll
    for (int o = 16; o; o >>= 1) sk += __shfl_xor_sync(0xffffffffu, sk, o);
    float kn = yk / fmaxf(sqrtf(sk), 1e-12f);

    float scale = log1pf(expf(temp[h])) * sls[n];
    float qs = (qn + qe[c]) * scale;

    g_kn[bn*CC + c] = kn;

    size_t hm = ((size_t)(b*NHH + h)*NTOK + n)*HDD + d;
    __nv_bfloat16 qh = __float2bfloat16(qs);
    g_qshh[hm] = qh;
    g_qshl[hm] = __float2bfloat16(qs - __bfloat162float(qh));
}

// ---------------- learnable-token precompute (qs reconstructed from bf16 pair) ----------------
__global__ void alt_kernel(const float* __restrict__ lt_g, const float* __restrict__ lb_g,
                           const float* __restrict__ qe, const float* __restrict__ temp,
                           const float* __restrict__ sls)
{
    __shared__ float lts[NHH*HDD*LL];
    __shared__ float lbs[NHH*LL];
    __shared__ float qelt[NHH*LL];
    __shared__ float sp[NHH];
    int tid = threadIdx.x;
    for (int i = tid; i < NHH*HDD*LL; i += 256) lts[i] = lt_g[i];
    if (tid < NHH*LL) lbs[tid] = lb_g[tid];
    if (tid < NHH) sp[tid] = log1pf(expf(temp[tid]));
    __syncthreads();
    if (tid < NHH*LL) {
        int h = tid / LL, l = tid % LL;
        float s = 0.f;
        for (int d = 0; d < HDD; d++)
            s += qe[h*HDD + d] * lts[(h*HDD + d)*LL + l];
        qelt[tid] = s;
    }
    __syncthreads();

    int idx = blockIdx.x * 256 + tid;
    int bn = idx >> 3, h = idx & 7;
    int b = bn >> 12, n = bn & (NTOK - 1);

    const size_t qoff = ((size_t)(b*NHH + h)*NTOK + n)*HDD;
    const __nv_bfloat16* qh = g_qshh + qoff;
    const __nv_bfloat16* ql = g_qshl + qoff;

    float invs = 1.f / (sp[h] * sls[n]);
    float acc[LL];
    #pragma unroll
    for (int l = 0; l < LL; l++) acc[l] = 0.f;
    #pragma unroll 4
    for (int d = 0; d < HDD; d++) {
        float q = __bfloat162float(qh[d]) + __bfloat162float(ql[d]);
        #pragma unroll
        for (int l = 0; l < LL; l++)
            acc[l] = fmaf(q, lts[(h*HDD + d)*LL + l], acc[l]);
    }
    float* outp = g_alt + (size_t)idx * 12;
    #pragma unroll
    for (int l = 0; l < LL; l++)
        outp[l] = acc[l] * invs - qelt[h*LL + l] + lbs[h*LL + l];
    outp[9] = 0.f; outp[10] = 0.f; outp[11] = 0.f;
}

// ---------------- 8x8 avg pool + layernorm ----------------
__global__ void pool_ln_kernel(const float* __restrict__ ng,
                               const float* __restrict__ nb)
{
    int bp = blockIdx.x;
    int b  = bp >> 6, p = bp & 63;
    int ph = p >> 3, pw = p & 7;
    int c  = threadIdx.x;

    float s = 0.f;
    for (int r = 0; r < 8; r++)
        #pragma unroll
        for (int q = 0; q < 8; q++) {
            int n = (ph*8 + r) * 64 + pw*8 + q;
            s += g_big[(size_t)(b*NTOK + n)*1024 + 768 + c];
        }
    float avg = s * (1.f/64.f);

    float v1 = avg, v2 = avg*avg;
    #pragma unroll
    for (int o = 16; o; o >>= 1) {
        v1 += __shfl_xor_sync(0xffffffffu, v1, o);
        v2 += __shfl_xor_sync(0xffffffffu, v2, o);
    }
    __shared__ float s1[8], s2[8];
    int w = c >> 5, lane = c & 31;
    if (lane == 0) { s1[w] = v1; s2[w] = v2; }
    __syncthreads();
    float m1 = 0.f, m2 = 0.f;
    #pragma unroll
    for (int ww = 0; ww < 8; ww++) { m1 += s1[ww]; m2 += s2[ww]; }
    m1 *= (1.f/256.f); m2 *= (1.f/256.f);
    float var = m2 - m1*m1;
    g_pln[bp*CC + c] = (avg - m1) * rsqrtf(var + 1e-5f) * ng[c] + nb[c];
}

// ---------------- pooled kv projection -> bf16 splits ----------------
__global__ void kvpool_kernel(const float* __restrict__ kv_w,
                              const float* __restrict__ kv_b)
{
    int bp = blockIdx.x; int b = bp >> 6, p = bp & 63;
    __shared__ __align__(16) float xr[CC];
    int tid = threadIdx.x;
    if (tid < CC) xr[tid] = g_pln[bp*CC + tid];
    __syncthreads();

    int o = tid;
    float acc = kv_b[o];
    const float4* w4 = (const float4*)(kv_w + (size_t)o * CC);
    const float4* x4 = (const float4*)xr;
    #pragma unroll 8
    for (int k = 0; k < 64; k++) {
        float4 w = w4[k], xv = x4[k];
        acc += w.x*xv.x + w.y*xv.y + w.z*xv.z + w.w*xv.w;
    }
    int lane = tid & 31;
    if (o < CC) {
        float s = acc*acc;
        #pragma unroll
        for (int q = 16; q; q >>= 1) s += __shfl_xor_sync(0xffffffffu, s, q);
        float kn = acc / fmaxf(sqrtf(s), 1e-12f);
        int h = o >> 5;
        size_t idx = ((size_t)(b*NHH + h)*PP + p)*HDD + lane;
        __nv_bfloat16 kh = __float2bfloat16(kn);
        g_kph[idx] = kh;
        g_kpl[idx] = __float2bfloat16(kn - __bfloat162float(kh));
    } else {
        int oo = o - CC; int h = oo >> 5, d = oo & 31;
        size_t idx = ((size_t)(b*NHH + h)*HDD + d)*PP + p;
        __nv_bfloat16 vh = __float2bfloat16(acc);
        g_vth[idx] = vh;
        g_vtl[idx] = __float2bfloat16(acc - __bfloat162float(vh));
    }
}

// ---------------- CPB MLP ----------------
__global__ void cpb_kernel(const float* __restrict__ table,
                           const float* __restrict__ w1, const float* __restrict__ b1,
                           const float* __restrict__ w2, const float* __restrict__ b2)
{
    __shared__ float sw1[1024], sb1[512], sw2[4096];
    int tid = threadIdx.x;
    for (int i = tid; i < 1024; i += 128) sw1[i] = w1[i];
    for (int i = tid; i <  512; i += 128) sb1[i] = b1[i];
    for (int i = tid; i < 4096; i += 128) sw2[i] = w2[i];
    __syncthreads();

    int t = blockIdx.x * 128 + tid;
    float c0 = table[2*t], c1 = table[2*t+1];
    float acc[NHH];
    #pragma unroll
    for (int h = 0; h < NHH; h++) acc[h] = b2[h];
    for (int j = 0; j < 512; j++) {
        float hj = fmaxf(fmaf(c0, sw1[2*j], fmaf(c1, sw1[2*j+1], sb1[j])), 0.f);
        #pragma unroll
        for (int h = 0; h < NHH; h++) acc[h] = fmaf(hj, sw2[h*512 + j], acc[h]);
    }
    #pragma unroll
    for (int h = 0; h < NHH; h++) g_cpb[t*NHH + h] = acc[h];
}

// ---------------- pool bias gather ----------------
__global__ void pbias_kernel(const int* __restrict__ rpi)
{
    int n = blockIdx.x, tid = threadIdx.x;
    int h = tid >> 6, p = tid & 63;
    int r = rpi[n*PP + p];
    g_pb[(size_t)n*512 + tid] = g_cpb[r*NHH + h];
}

// ---------------- pool logits mma ----------------
__global__ __launch_bounds__(128) void pool_logits_mma()
{
    __shared__ __align__(128) char smem[24576];
    const uint32_t sb = smem_u32(smem);
    const int tid = threadIdx.x, w = tid >> 5, lane = tid & 31;
    const int bh = blockIdx.y, m0 = blockIdx.x * 128;
    const int h = bh & 7;
    const uint32_t A0 = 0, A1 = 8192, B0 = 16384, B1 = 20480;

    #pragma unroll
    for (int it = 0; it < 4; it++) {
        int idx = it*128 + tid, row = idx >> 2, ch = idx & 3;
        uint32_t so = (uint32_t)row*64 + (uint32_t)((ch ^ (row & 3))*16);
        const size_t src = ((size_t)bh*NTOK + m0 + row)*HDD + ch*8;
        cp_async16(sb + A0 + so, g_qshh + src);
        cp_async16(sb + A1 + so, g_qshl + src);
    }
    #pragma unroll
    for (int it = 0; it < 2; it++) {
        int idx = it*128 + tid, row = idx >> 2, ch = idx & 3;
        uint32_t so = (uint32_t)row*64 + (uint32_t)((ch ^ (row & 3))*16);
        const size_t src = ((size_t)bh*PP + row)*HDD + ch*8;
        cp_async16(sb + B0 + so, g_kph + src);
        cp_async16(sb + B1 + so, g_kpl + src);
    }
    CP_COMMIT(); CP_WAIT0();
    __syncthreads();

    float acc[2][8][4];
    #pragma unroll
    for (int i = 0; i < 2; i++)
        #pragma unroll
        for (int j = 0; j < 8; j++)
            #pragma unroll
            for (int e = 0; e < 4; e++) acc[i][j][e] = 0.f;

    #pragma unroll
    for (int pass = 0; pass < 3; pass++) {
        const uint32_t ab = sb + ((pass == 2) ? A1 : A0);
        const uint32_t bb = sb + ((pass == 1) ? B1 : B0);
        #pragma unroll
        for (int ks = 0; ks < 2; ks++) {
            uint32_t afr[2][4];
            #pragma unroll
            for (int tm = 0; tm < 2; tm++) {
                int row = w*32 + tm*16 + (lane & 15);
                int cc  = ks*2 + (lane >> 4);
                ldmx4(afr[tm], ab + (uint32_t)row*64 + (uint32_t)((cc ^ (row & 3))*16));
            }
            uint32_t bfr[4][4];
            #pragma unroll
            for (int tp = 0; tp < 4; tp++) {
                int g = lane >> 3;
                int row = tp*16 + ((g >> 1) & 1)*8 + (lane & 7);
                int cc  = ks*2 + (g & 1);
                ldmx4(bfr[tp], bb + (uint32_t)row*64 + (uint32_t)((cc ^ (row & 3))*16));
            }
            #pragma unroll
            for (int tm = 0; tm < 2; tm++)
                #pragma unroll
                for (int tn = 0; tn < 8; tn++)
                    mma16816(acc[tm][tn], afr[tm],
                             bfr[tn >> 1][(tn & 1)*2], bfr[tn >> 1][(tn & 1)*2 + 1]);
        }
    }

    #pragma unroll
    for (int tm = 0; tm < 2; tm++) {
        int gn = m0 + w*32 + tm*16 + (lane >> 2);
        #pragma unroll
        for (int tn = 0; tn < 8; tn++) {
            int p = tn*8 + 2*(lane & 3);
            float2 pb0 = *(const float2*)&g_pb[(size_t)gn*512 + h*64 + p];
            float2 pb1 = *(const float2*)&g_pb[(size_t)(gn+8)*512 + h*64 + p];
            *(float2*)&g_S[((size_t)bh*NTOK + gn)*PP + p] =
                make_float2(acc[tm][tn][0] + pb0.x, acc[tm][tn][1] + pb0.y);
            *(float2*)&g_S[((size_t)bh*NTOK + gn + 8)*PP + p] =
                make_float2(acc[tm][tn][2] + pb1.x, acc[tm][tn][3] + pb1.y);
        }
    }
}

// ---------------- attn6: local logits + joint softmax ----------------
__global__ __launch_bounds__(256) void attn_kernel6(const float* __restrict__ rpb_g)
{
    const int tid = threadIdx.x;
    const int bh = blockIdx.y, b = bh >> 3, h = bh & 7, chunk = blockIdx.x;
    const int w = tid >> 5, lane = tid & 31;
    const int tsub = lane >> 3, dg = lane & 7;

    float rpbl[LL];
    #pragma unroll
    for (int l = 0; l < LL; l++) rpbl[l] = rpb_g[h*LL + l];

    for (int s = 0; s < 8; s++) {
        const int n = chunk*256 + w*32 + s*4 + tsub;
        const int i = n >> 6, j = n & 63;

        // q reconstructed from head-major bf16 hi/lo pair
        const size_t qoff = ((size_t)bh*NTOK + n)*HDD + dg*4;
        uint2 uh = *(const uint2*)(g_qshh + qoff);
        uint2 ul = *(const uint2*)(g_qshl + qoff);
        float2 h01 = bf2f(uh.x), h23 = bf2f(uh.y);
        float2 l01 = bf2f(ul.x), l23 = bf2f(ul.y);
        float4 qv = make_float4(h01.x + l01.x, h01.y + l01.y,
                                h23.x + l23.x, h23.y + l23.y);

        float el[LL];
        bool  vlm[LL];
        #pragma unroll
        for (int l = 0; l < LL; l++) {
            int ii = i + l/3 - 1, jj = j + l%3 - 1;
            vlm[l] = ((unsigned)ii < 64u) && ((unsigned)jj < 64u);
            float sv = 0.f;
            if (vlm[l]) {
                float4 k4 = *(const float4*)(g_kn +
                    (size_t)(b*NTOK + ii*64 + jj)*CC + h*HDD + dg*4);
                sv = qv.x*k4.x + qv.y*k4.y + qv.z*k4.z + qv.w*k4.w;
            }
            el[l] = sv;
        }
        #pragma unroll
        for (int l = 0; l < LL; l++) {
            float sv = el[l];
            sv += __shfl_xor_sync(0xffffffffu, sv, 1);
            sv += __shfl_xor_sync(0xffffffffu, sv, 2);
            sv += __shfl_xor_sync(0xffffffffu, sv, 4);
            el[l] = vlm[l] ? (sv + rpbl[l]) : -1e30f;
        }

        const float* Sp = g_S + ((size_t)bh*NTOK + n)*PP + dg*8;
        float4 s03 = *(const float4*)Sp;
        float4 s47 = *(const float4*)(Sp + 4);
        float pl[8] = { s03.x, s03.y, s03.z, s03.w, s47.x, s47.y, s47.z, s47.w };

        float m = el[0];
        #pragma unroll
        for (int l = 1; l < LL; l++) m = fmaxf(m, el[l]);
        #pragma unroll
        for (int p = 0; p < 8; p++) m = fmaxf(m, pl[p]);
        m = fmaxf(m, __shfl_xor_sync(0xffffffffu, m, 1));
        m = fmaxf(m, __shfl_xor_sync(0xffffffffu, m, 2));
        m = fmaxf(m, __shfl_xor_sync(0xffffffffu, m, 4));

        float els = 0.f;
        #pragma unroll
        for (int l = 0; l < LL; l++) { el[l] = __expf(el[l] - m); els += el[l]; }
        float pes = 0.f;
        #pragma unroll
        for (int p = 0; p < 8; p++) { pl[p] = __expf(pl[p] - m); pes += pl[p]; }
        pes += __shfl_xor_sync(0xffffffffu, pes, 1);
        pes += __shfl_xor_sync(0xffffffffu, pes, 2);
        pes += __shfl_xor_sync(0xffffffffu, pes, 4);
        float inv = 1.f / (pes + els);

        {
            float wv[8], lv[8];
            #pragma unroll
            for (int p = 0; p < 8; p++) {
                wv[p] = pl[p] * inv;
                float hi = __bfloat162float(__float2bfloat16(wv[p]));
                lv[p] = wv[p] - hi;
            }
            uint4 xh4, xl4;
            xh4.x = pack_bf2(wv[0], wv[1]); xh4.y = pack_bf2(wv[2], wv[3]);
            xh4.z = pack_bf2(wv[4], wv[5]); xh4.w = pack_bf2(wv[6], wv[7]);
            xl4.x = pack_bf2(lv[0], lv[1]); xl4.y = pack_bf2(lv[2], lv[3]);
            xl4.z = pack_bf2(lv[4], lv[5]); xl4.w = pack_bf2(lv[6], lv[7]);
            size_t off = ((size_t)bh*NTOK + n)*PP + dg*8;
            *(uint4*)(g_apwh + off) = xh4;
            *(uint4*)(g_apwl + off) = xl4;
        }

        const float* altp = g_alt + ((size_t)(b*NTOK + n)*NHH + h)*12;
        float4 a03 = *(const float4*)altp;
        float4 a47 = *(const float4*)(altp + 4);
        float  a8  = altp[8];
        float av[LL] = { a03.x, a03.y, a03.z, a03.w, a47.x, a47.y, a47.z, a47.w, a8 };
        #pragma unroll
        for (int l = 0; l < LL; l++) av[l] += el[l]*inv;

        float4 xo = make_float4(0.f, 0.f, 0.f, 0.f);
        #pragma unroll
        for (int l = 0; l < LL; l++) {
            if (vlm[l]) {
                int ii = i + l/3 - 1, jj = j + l%3 - 1;
                float4 v4 = *(const float4*)(g_big +
                    (size_t)(b*NTOK + ii*64 + jj)*1024 + 512 + h*HDD + dg*4);
                xo.x = fmaf(av[l], v4.x, xo.x);
                xo.y = fmaf(av[l], v4.y, xo.y);
                xo.z = fmaf(av[l], v4.z, xo.z);
                xo.w = fmaf(av[l], v4.w, xo.w);
            }
        }
        *(float4*)(g_xloc + ((size_t)bh*NTOK + n)*HDD + dg*4) = xo;
    }
}

// ---------------- pool output mma ----------------
__global__ __launch_bounds__(128) void pool_out_mma()
{
    __shared__ __align__(128) char smem[40960];
    const uint32_t sb = smem_u32(smem);
    const int tid = threadIdx.x, w = tid >> 5, lane = tid & 31;
    const int bh = blockIdx.y, m0 = blockIdx.x * 128;
    const int b = bh >> 3, h = bh & 7;
    const uint32_t A0 = 0, A1 = 16384, B0 = 32768, B1 = 36864;

    #pragma unroll
    for (int it = 0; it < 8; it++) {
        int idx = it*128 + tid, row = idx >> 3, ch = idx & 7;
        uint32_t so = (uint32_t)row*128 + (uint32_t)((ch ^ (row & 7))*16);
        const size_t src = ((size_t)bh*NTOK + m0 + row)*PP + ch*8;
        cp_async16(sb + A0 + so, g_apwh + src);
        cp_async16(sb + A1 + so, g_apwl + src);
    }
    #pragma unroll
    for (int it = 0; it < 2; it++) {
        int idx = it*128 + tid, row = idx >> 3, ch = idx & 7;
        uint32_t so = (uint32_t)row*128 + (uint32_t)((ch ^ (row & 7))*16);
        const size_t src = ((size_t)bh*HDD + row)*PP + ch*8;
        cp_async16(sb + B0 + so, g_vth + src);
        cp_async16(sb + B1 + so, g_vtl + src);
    }
    CP_COMMIT(); CP_WAIT0();
    __syncthreads();

    float acc[2][4][4];
    #pragma unroll
    for (int i = 0; i < 2; i++)
        #pragma unroll
        for (int j = 0; j < 4; j++)
            #pragma unroll
            for (int e = 0; e < 4; e++) acc[i][j][e] = 0.f;

    #pragma unroll
    for (int pass = 0; pass < 3; pass++) {
        const uint32_t ab = sb + ((pass == 2) ? A1 : A0);
        const uint32_t bb = sb + ((pass == 1) ? B1 : B0);
        #pragma unroll
        for (int ks = 0; ks < 4; ks++) {
            uint32_t afr[2][4];
            #pragma unroll
            for (int tm = 0; tm < 2; tm++) {
                int row = w*32 + tm*16 + (lane & 15);
                int cc  = ks*2 + (lane >> 4);
                ldmx4(afr[tm], ab + (uint32_t)row*128 + (uint32_t)((cc ^ (row & 7))*16));
            }
            uint32_t bfr[2][4];
            #pragma unroll
            for (int tp = 0; tp < 2; tp++) {
                int g = lane >> 3;
                int row = tp*16 + ((g >> 1) & 1)*8 + (lane & 7);
                int cc  = ks*2 + (g & 1);
                ldmx4(bfr[tp], bb + (uint32_t)row*128 + (uint32_t)((cc ^ (row & 7))*16));
            }
            #pragma unroll
            for (int tm = 0; tm < 2; tm++)
                #pragma unroll
                for (int tn = 0; tn < 4; tn++)
                    mma16816(acc[tm][tn], afr[tm],
                             bfr[tn >> 1][(tn & 1)*2], bfr[tn >> 1][(tn & 1)*2 + 1]);
        }
    }

    #pragma unroll
    for (int tm = 0; tm < 2; tm++) {
        #pragma unroll
        for (int half = 0; half < 2; half++) {
            int gn = m0 + w*32 + tm*16 + (lane >> 2) + half*8;
            #pragma unroll
            for (int tn = 0; tn < 4; tn++) {
                int d = tn*8 + 2*(lane & 3);
                float2 x2 = *(const float2*)&g_xloc[((size_t)bh*NTOK + gn)*HDD + d];
                float r0 = acc[tm][tn][half*2 + 0] + x2.x;
                float r1 = acc[tm][tn][half*2 + 1] + x2.y;
                __nv_bfloat16 h0 = __float2bfloat16(r0), h1 = __float2bfloat16(r1);
                size_t off = (size_t)(b*NTOK + gn)*CC + h*HDD + d;
                *(uint32_t*)(g_ath + off) = pack_bf2(r0, r1);
                *(uint32_t*)(g_atl + off) = pack_bf2(r0 - __bfloat162float(h0),
                                                     r1 - __bfloat162float(h1));
            }
        }
    }
}

// ---------------- launch ----------------
extern "C" void kernel_launch(void* const* d_in, const int* in_sizes, int n_in,
                              void* d_out, int out_size)
{
    const float* x      = (const float*)d_in[0];
    const int*   rpi    = (const int*)  d_in[1];
    const float* table  = (const float*)d_in[2];
    const float* q_w    = (const float*)d_in[3];
    const float* q_b    = (const float*)d_in[4];
    const float* kv_w   = (const float*)d_in[5];
    const float* kv_b   = (const float*)d_in[6];
    const float* temp   = (const float*)d_in[7];
    const float* qe     = (const float*)d_in[8];
    const float* proj_w = (const float*)d_in[9];
    const float* proj_b = (const float*)d_in[10];
    const float* sr_w   = (const float*)d_in[11];
    const float* sr_b   = (const float*)d_in[12];
    const float* norm_g = (const float*)d_in[13];
    const float* norm_b = (const float*)d_in[14];
    const float* cpb1_w = (const float*)d_in[15];
    const float* cpb1_b = (const float*)d_in[16];
    const float* cpb2_w = (const float*)d_in[17];
    const float* cpb2_b = (const float*)d_in[18];
    const float* rpb    = (const float*)d_in[19];
    const float* lt     = (const float*)d_in[20];
    const float* lb     = (const float*)d_in[21];
    const float* sls    = (const float*)d_in[22];
    float* out = (float*)d_out;

    void *p_big, *p_xh, *p_xl, *p_ath, *p_atl, *p_wbh, *p_wbl, *p_pwh, *p_pwl, *p_bigb;
    cudaGetSymbolAddress(&p_big,  g_big);
    cudaGetSymbolAddress(&p_xh,   g_xh);  cudaGetSymbolAddress(&p_xl,  g_xl);
    cudaGetSymbolAddress(&p_ath,  g_ath); cudaGetSymbolAddress(&p_atl, g_atl);
    cudaGetSymbolAddress(&p_wbh,  g_wbh); cudaGetSymbolAddress(&p_wbl, g_wbl);
    cudaGetSymbolAddress(&p_pwh,  g_pwh); cudaGetSymbolAddress(&p_pwl, g_pwl);
    cudaGetSymbolAddress(&p_bigb, g_bigb);

    const int M = BB * NTOK;
    const int NX = M * CC;

    cudaFuncSetAttribute(gemm_mma, cudaFuncAttributeMaxDynamicSharedMemorySize, GS_TOT);

    #define BF(p) ((__nv_bfloat16*)(p))
    cvt_hilo<<<(NX+255)/256, 256>>>(x, BF(p_xh), BF(p_xl), NX);
    cvt_weights<<<(NW + NPJ + 1024 + 255)/256, 256>>>(q_w, kv_w, sr_w, proj_w,
                                                      q_b, kv_b, sr_b);
    cpb_kernel<<<TT/128, 128>>>(table, cpb1_w, cpb1_b, cpb2_w, cpb2_b);
    gemm_mma<<<dim3(8, M/128), 256, GS_TOT>>>(BF(p_xh), BF(p_xl), BF(p_wbh), BF(p_wbl),
                                              (float*)p_bigb, (float*)p_big, 1024, 2);

    normalize_kernel<<<M, CC>>>(qe, temp, sls);
    pool_ln_kernel<<<BB*PP, CC>>>(norm_g, norm_b);
    kvpool_kernel<<<BB*PP, 512>>>(kv_w, kv_b);
    pbias_kernel<<<NTOK, 512>>>(rpi);
    alt_kernel<<<(M*NHH)/256, 256>>>(lt, lb, qe, temp, sls);

    pool_logits_mma<<<dim3(NTOK/128, BB*NHH), 128>>>();
    attn_kernel6<<<dim3(16, BB*NHH), 256>>>(rpb);
    pool_out_mma<<<dim3(NTOK/128, BB*NHH), 128>>>();

    gemm_mma<<<dim3(2, M/128), 256, GS_TOT>>>(BF(p_ath), BF(p_atl), BF(p_pwh), BF(p_pwl),
                                              proj_b, out, CC, 0);
    #undef BF
}

// round 16
// speedup vs baseline: 1.0431x; 1.0129x over previous
#include <cuda_runtime.h>
#include <cuda_bf16.h>
#include <cstdint>

#define BB   4
#define NTOK 4096
#define CC   256
#define NHH  8
#define HDD  32
#define LL   9
#define PP   64
#define TT   4096

// ---------------- scratch ----------------
__device__ float g_big  [BB*NTOK*1024];    // [q | k | v | xs]
__device__ float g_kn   [BB*NHH*NTOK*HDD]; // head-major [bh][n][d]
__device__ float g_cpb  [TT*NHH];
__device__ float g_pb   [NTOK*NHH*PP];     // [n][h][p]
__device__ float g_alt  [BB*NTOK*NHH*12];
__device__ float g_S    [BB*NHH*NTOK*PP];  // pool logits (+bias)
__device__ float g_xloc [BB*NHH*NTOK*HDD]; // local-path output

// bf16 operands
__device__ __nv_bfloat16 g_xh [BB*NTOK*CC], g_xl [BB*NTOK*CC];
__device__ __nv_bfloat16 g_ath[BB*NTOK*CC], g_atl[BB*NTOK*CC];
__device__ __nv_bfloat16 g_wbh[1024*CC],    g_wbl[1024*CC];
__device__ __nv_bfloat16 g_pwh[CC*CC],      g_pwl[CC*CC];
__device__ float         g_bigb[1024];
__device__ __nv_bfloat16 g_qshh[BB*NHH*NTOK*HDD], g_qshl[BB*NHH*NTOK*HDD]; // [bh][n][d]
__device__ __nv_bfloat16 g_kph [BB*NHH*PP*HDD],   g_kpl [BB*NHH*PP*HDD];
__device__ __nv_bfloat16 g_vth [BB*NHH*HDD*PP],   g_vtl [BB*NHH*HDD*PP];
__device__ __nv_bfloat16 g_apwh[BB*NHH*NTOK*PP],  g_apwl[BB*NHH*NTOK*PP];

// ---------------- helpers ----------------
__device__ __forceinline__ uint32_t smem_u32(const void* p) {
    uint32_t a;
    asm("{ .reg .u64 t; cvta.to.shared.u64 t, %1; cvt.u32.u64 %0, t; }" : "=r"(a) : "l"(p));
    return a;
}
__device__ __forceinline__ void cp_async16(uint32_t dst, const void* src) {
    asm volatile("cp.async.cg.shared.global [%0], [%1], 16;" :: "r"(dst), "l"(src) : "memory");
}
#define CP_COMMIT() asm volatile("cp.async.commit_group;" ::: "memory")
#define CP_WAIT0()  asm volatile("cp.async.wait_group 0;" ::: "memory")

__device__ __forceinline__ void ldmx4(uint32_t* r, uint32_t addr) {
    asm volatile("ldmatrix.sync.aligned.m8n8.x4.shared.b16 {%0,%1,%2,%3}, [%4];"
                 : "=r"(r[0]), "=r"(r[1]), "=r"(r[2]), "=r"(r[3]) : "r"(addr));
}
__device__ __forceinline__ void mma16816(float* c, const uint32_t* a, uint32_t b0, uint32_t b1) {
    asm volatile("mma.sync.aligned.m16n8k16.row.col.f32.bf16.bf16.f32 "
                 "{%0,%1,%2,%3}, {%4,%5,%6,%7}, {%8,%9}, {%0,%1,%2,%3};"
                 : "+f"(c[0]), "+f"(c[1]), "+f"(c[2]), "+f"(c[3])
                 : "r"(a[0]), "r"(a[1]), "r"(a[2]), "r"(a[3]), "r"(b0), "r"(b1));
}
__device__ __forceinline__ uint32_t pack_bf2(float a, float b) {
    __nv_bfloat162 t = __floats2bfloat162_rn(a, b);
    return *(uint32_t*)&t;
}
__device__ __forceinline__ float2 bf2f(uint32_t u) {
    __nv_bfloat162 t = *(__nv_bfloat162*)&u;
    return make_float2(__bfloat162float(t.x), __bfloat162float(t.y));
}

// ---------------- x hi/lo split ----------------
__global__ void cvt_hilo(const float* __restrict__ src,
                         __nv_bfloat16* __restrict__ hi,
                         __nv_bfloat16* __restrict__ lo, int n)
{
    int i = blockIdx.x * 256 + threadIdx.x;
    if (i < n) {
        float v = src[i];
        __nv_bfloat16 h = __float2bfloat16(v);
        hi[i] = h;
        lo[i] = __float2bfloat16(v - __bfloat162float(h));
    }
}

// ---------------- fused weight conversion ----------------
#define NW (1024*CC)
#define NPJ (CC*CC)
__global__ void cvt_weights(const float* __restrict__ qw, const float* __restrict__ kvw,
                            const float* __restrict__ srw, const float* __restrict__ pjw,
                            const float* __restrict__ qb, const float* __restrict__ kvb,
                            const float* __restrict__ srb)
{
    int idx = blockIdx.x * 256 + threadIdx.x;
    if (idx < NW) {
        int row = idx >> 8, col = idx & 255;
        float v = (row < 256) ? qw[row*256 + col]
                : (row < 768) ? kvw[(row-256)*256 + col]
                              : srw[(row-768)*256 + col];
        __nv_bfloat16 h = __float2bfloat16(v);
        g_wbh[idx] = h;
        g_wbl[idx] = __float2bfloat16(v - __bfloat162float(h));
    } else if (idx < NW + NPJ) {
        int j = idx - NW;
        float v = pjw[j];
        __nv_bfloat16 h = __float2bfloat16(v);
        g_pwh[j] = h;
        g_pwl[j] = __float2bfloat16(v - __bfloat162float(h));
    } else if (idx < NW + NPJ + 1024) {
        int j = idx - NW - NPJ;
        g_bigb[j] = (j < 256) ? qb[j] : (j < 768) ? kvb[j-256] : srb[j-768];
    }
}

// ---------------- HMMA GEMM (proven; at mma.sync floor) ----------------
#define GS_A0   0
#define GS_A1   16384
#define GS_W0   32768
#define GS_W1   49152
#define GS_BIAS 65536
#define GS_TOT  66048

__global__ __launch_bounds__(256) void gemm_mma(
    const __nv_bfloat16* __restrict__ Ah, const __nv_bfloat16* __restrict__ Al,
    const __nv_bfloat16* __restrict__ Wh, const __nv_bfloat16* __restrict__ Wl,
    const float* __restrict__ bias, float* __restrict__ Y, int Nout, int act)
{
    extern __shared__ __align__(128) char smem[];
    const uint32_t sb = smem_u32(smem);
    float* sbias = (float*)(smem + GS_BIAS);

    const int tid = threadIdx.x, wid = tid >> 5, lane = tid & 31;
    const int n0 = blockIdx.x * 128, m0 = blockIdx.y * 128;
    const int warp_m = wid & 1, warp_n = wid >> 1;
    const bool do_gelu = (act == 1) || (act == 2 && n0 >= 768);

    if (tid < 128) sbias[tid] = bias[n0 + tid];

    float acc[4][4][4];
    #pragma unroll
    for (int i = 0; i < 4; i++)
        #pragma unroll
        for (int j = 0; j < 4; j++)
            #pragma unroll
            for (int e = 0; e < 4; e++) acc[i][j][e] = 0.f;

    const int lrow0 = tid >> 3;
    const int luc   = tid & 7;

    auto issue = [&](int c, int buf) {
        int seg = c >> 2, ks0 = (c & 3) * 64;
        const __nv_bfloat16* Asrc = (seg < 2) ? Ah : Al;
        const __nv_bfloat16* Wsrc = (seg == 1) ? Wl : Wh;
        uint32_t ab = sb + (buf ? GS_A1 : GS_A0);
        uint32_t wb = sb + (buf ? GS_W1 : GS_W0);
        #pragma unroll
        for (int i = 0; i < 4; i++) {
            int row = lrow0 + i * 32;
            uint32_t soff = (uint32_t)row * 128 + (uint32_t)((luc ^ (row & 7)) * 16);
            cp_async16(ab + soff, Asrc + (size_t)(m0 + row) * CC + ks0 + luc * 8);
            cp_async16(wb + soff, Wsrc + (size_t)(n0 + row) * CC + ks0 + luc * 8);
        }
        CP_COMMIT();
    };

    issue(0, 0);

    for (int c = 0; c < 12; c++) {
        CP_WAIT0();
        __syncthreads();
        if (c + 1 < 12) issue(c + 1, (c + 1) & 1);

        const uint32_t ab = sb + ((c & 1) ? GS_A1 : GS_A0);
        const uint32_t wb = sb + ((c & 1) ? GS_W1 : GS_W0);

        #pragma unroll
        for (int ks = 0; ks < 4; ks++) {
            uint32_t afr[4][4];
            #pragma unroll
            for (int tm = 0; tm < 4; tm++) {
                int row = warp_m * 64 + tm * 16 + (lane & 15);
                int cc  = ks * 2 + (lane >> 4);
                ldmx4(afr[tm], ab + (uint32_t)row * 128 + (uint32_t)((cc ^ (row & 7)) * 16));
            }
            uint32_t bfr[2][4];
            #pragma unroll
            for (int tp = 0; tp < 2; tp++) {
                int g = lane >> 3;
                int row = warp_n * 32 + tp * 16 + ((g >> 1) & 1) * 8 + (lane & 7);
                int cc  = ks * 2 + (g & 1);
                ldmx4(bfr[tp], wb + (uint32_t)row * 128 + (uint32_t)((cc ^ (row & 7)) * 16));
            }
            #pragma unroll
            for (int tm = 0; tm < 4; tm++)
                #pragma unroll
                for (int tn = 0; tn < 4; tn++)
                    mma16816(acc[tm][tn], afr[tm],
                             bfr[tn >> 1][(tn & 1) * 2], bfr[tn >> 1][(tn & 1) * 2 + 1]);
        }
    }

    #pragma unroll
    for (int tm = 0; tm < 4; tm++) {
        int gr = m0 + warp_m * 64 + tm * 16 + (lane >> 2);
        #pragma unroll
        for (int tn = 0; tn < 4; tn++) {
            int lc = warp_n * 32 + tn * 8 + 2 * (lane & 3);
            int gc = n0 + lc;
            float b0 = sbias[lc], b1 = sbias[lc + 1];
            float r0 = acc[tm][tn][0] + b0, r1 = acc[tm][tn][1] + b1;
            float r2 = acc[tm][tn][2] + b0, r3 = acc[tm][tn][3] + b1;
            if (do_gelu) {
                r0 *= normcdff(r0); r1 *= normcdff(r1);
                r2 *= normcdff(r2); r3 *= normcdff(r3);
            }
            *(float2*)&Y[(size_t)gr * Nout + gc]       = make_float2(r0, r1);
            *(float2*)&Y[(size_t)(gr + 8) * Nout + gc] = make_float2(r2, r3);
        }
    }
}

// ---------------- normalize: kn head-major fp32 + qs bf16 hi/lo head-major ----------------
__global__ void normalize_kernel(const float* __restrict__ qe,
                                 const float* __restrict__ temp,
                                 const float* __restrict__ sls)
{
    int bn = blockIdx.x;
    int n  = bn & (NTOK - 1);
    int b  = bn >> 12;
    int c  = threadIdx.x;
    int h  = c >> 5, d = c & 31;

    float yq = g_big[(size_t)bn*1024 + c];
    float yk = g_big[(size_t)bn*1024 + 256 + c];

    float sq = yq*yq;
    #pragma unroll
    for (int o = 16; o; o >>= 1) sq += __shfl_xor_sync(0xffffffffu, sq, o);
    float qn = yq / fmaxf(sqrtf(sq), 1e-12f);

    float sk = yk*yk;
    #pragma unroll
    for (int o = 16; o; o >>= 1) sk += __shfl_xor_sync(0xffffffffu, sk, o);
    float kn = yk / fmaxf(sqrtf(sk), 1e-12f);

    float scale = log1pf(expf(temp[h])) * sls[n];
    float qs = (qn + qe[c]) * scale;

    size_t hm = ((size_t)(b*NHH + h)*NTOK + n)*HDD + d;
    g_kn[hm] = kn;
    __nv_bfloat16 qh = __float2bfloat16(qs);
    g_qshh[hm] = qh;
    g_qshl[hm] = __float2bfloat16(qs - __bfloat162float(qh));
}

// ---------------- learnable-token precompute ----------------
__global__ void alt_kernel(const float* __restrict__ lt_g, const float* __restrict__ lb_g,
                           const float* __restrict__ qe, const float* __restrict__ temp,
                           const float* __restrict__ sls)
{
    __shared__ float lts[NHH*HDD*LL];
    __shared__ float lbs[NHH*LL];
    __shared__ float qelt[NHH*LL];
    __shared__ float sp[NHH];
    int tid = threadIdx.x;
    for (int i = tid; i < NHH*HDD*LL; i += 256) lts[i] = lt_g[i];
    if (tid < NHH*LL) lbs[tid] = lb_g[tid];
    if (tid < NHH) sp[tid] = log1pf(expf(temp[tid]));
    __syncthreads();
    if (tid < NHH*LL) {
        int h = tid / LL, l = tid % LL;
        float s = 0.f;
        for (int d = 0; d < HDD; d++)
            s += qe[h*HDD + d] * lts[(h*HDD + d)*LL + l];
        qelt[tid] = s;
    }
    __syncthreads();

    int idx = blockIdx.x * 256 + tid;
    int bn = idx >> 3, h = idx & 7;
    int b = bn >> 12, n = bn & (NTOK - 1);

    const size_t qoff = ((size_t)(b*NHH + h)*NTOK + n)*HDD;
    const __nv_bfloat16* qh = g_qshh + qoff;
    const __nv_bfloat16* ql = g_qshl + qoff;

    float invs = 1.f / (sp[h] * sls[n]);
    float acc[LL];
    #pragma unroll
    for (int l = 0; l < LL; l++) acc[l] = 0.f;
    #pragma unroll 4
    for (int d = 0; d < HDD; d++) {
        float q = __bfloat162float(qh[d]) + __bfloat162float(ql[d]);
        #pragma unroll
        for (int l = 0; l < LL; l++)
            acc[l] = fmaf(q, lts[(h*HDD + d)*LL + l], acc[l]);
    }
    float* outp = g_alt + (size_t)idx * 12;
    #pragma unroll
    for (int l = 0; l < LL; l++)
        outp[l] = acc[l] * invs - qelt[h*LL + l] + lbs[h*LL + l];
    outp[9] = 0.f; outp[10] = 0.f; outp[11] = 0.f;
}

// ---------------- fused pool+LN+kv projection ----------------
__global__ __launch_bounds__(512) void poolkv_kernel(
    const float* __restrict__ ng, const float* __restrict__ nb,
    const float* __restrict__ kv_w, const float* __restrict__ kv_b)
{
    __shared__ float psum[512];
    __shared__ __align__(16) float xr[CC];
    __shared__ float s1[8], s2[8];

    int bp = blockIdx.x; int b = bp >> 6, p = bp & 63;
    int ph = p >> 3, pw = p & 7;
    int tid = threadIdx.x;
    int c = tid & 255, half = tid >> 8;

    // phase 1: 2-way split pooling sum (32 tokens per thread)
    float s = 0.f;
    #pragma unroll
    for (int r = 0; r < 4; r++)
        #pragma unroll
        for (int q = 0; q < 8; q++) {
            int n = (ph*8 + half*4 + r) * 64 + pw*8 + q;
            s += g_big[(size_t)(b*NTOK + n)*1024 + 768 + c];
        }
    psum[tid] = s;
    __syncthreads();

    // phase 2: LN over 256 channels
    if (tid < 256) {
        float avg = (psum[c] + psum[c + 256]) * (1.f/64.f);
        float v1 = avg, v2 = avg*avg;
        #pragma unroll
        for (int o = 16; o; o >>= 1) {
            v1 += __shfl_xor_sync(0xffffffffu, v1, o);
            v2 += __shfl_xor_sync(0xffffffffu, v2, o);
        }
        int w = tid >> 5, lane = tid & 31;
        if (lane == 0) { s1[w] = v1; s2[w] = v2; }
        psum[tid] = avg;      // stash avg
    }
    __syncthreads();
    if (tid < 256) {
        float m1 = 0.f, m2 = 0.f;
        #pragma unroll
        for (int ww = 0; ww < 8; ww++) { m1 += s1[ww]; m2 += s2[ww]; }
        m1 *= (1.f/256.f); m2 *= (1.f/256.f);
        float var = m2 - m1*m1;
        xr[tid] = (psum[tid] - m1) * rsqrtf(var + 1e-5f) * ng[tid] + nb[tid];
    }
    __syncthreads();

    // phase 3: kv projection (512 outputs)
    int o = tid;
    float acc = kv_b[o];
    const float4* w4 = (const float4*)(kv_w + (size_t)o * CC);
    const float4* x4 = (const float4*)xr;
    #pragma unroll 8
    for (int k = 0; k < 64; k++) {
        float4 w = w4[k], xv = x4[k];
        acc += w.x*xv.x + w.y*xv.y + w.z*xv.z + w.w*xv.w;
    }
    int lane = tid & 31;
    if (o < CC) {
        float sv = acc*acc;
        #pragma unroll
        for (int q = 16; q; q >>= 1) sv += __shfl_xor_sync(0xffffffffu, sv, q);
        float kn = acc / fmaxf(sqrtf(sv), 1e-12f);
        int h = o >> 5;
        size_t idx = ((size_t)(b*NHH + h)*PP + p)*HDD + lane;
        __nv_bfloat16 kh = __float2bfloat16(kn);
        g_kph[idx] = kh;
        g_kpl[idx] = __float2bfloat16(kn - __bfloat162float(kh));
    } else {
        int oo = o - CC; int h = oo >> 5, d = oo & 31;
        size_t idx = ((size_t)(b*NHH + h)*HDD + d)*PP + p;
        __nv_bfloat16 vh = __float2bfloat16(acc);
        g_vth[idx] = vh;
        g_vtl[idx] = __float2bfloat16(acc - __bfloat162float(vh));
    }
}

// ---------------- CPB MLP ----------------
__global__ void cpb_kernel(const float* __restrict__ table,
                           const float* __restrict__ w1, const float* __restrict__ b1,
                           const float* __restrict__ w2, const float* __restrict__ b2)
{
    __shared__ float sw1[1024], sb1[512], sw2[4096];
    int tid = threadIdx.x;
    for (int i = tid; i < 1024; i += 128) sw1[i] = w1[i];
    for (int i = tid; i <  512; i += 128) sb1[i] = b1[i];
    for (int i = tid; i < 4096; i += 128) sw2[i] = w2[i];
    __syncthreads();

    int t = blockIdx.x * 128 + tid;
    float c0 = table[2*t], c1 = table[2*t+1];
    float acc[NHH];
    #pragma unroll
    for (int h = 0; h < NHH; h++) acc[h] = b2[h];
    for (int j = 0; j < 512; j++) {
        float hj = fmaxf(fmaf(c0, sw1[2*j], fmaf(c1, sw1[2*j+1], sb1[j])), 0.f);
        #pragma unroll
        for (int h = 0; h < NHH; h++) acc[h] = fmaf(hj, sw2[h*512 + j], acc[h]);
    }
    #pragma unroll
    for (int h = 0; h < NHH; h++) g_cpb[t*NHH + h] = acc[h];
}

// ---------------- pool bias gather ----------------
__global__ void pbias_kernel(const int* __restrict__ rpi)
{
    int n = blockIdx.x, tid = threadIdx.x;
    int h = tid >> 6, p = tid & 63;
    int r = rpi[n*PP + p];
    g_pb[(size_t)n*512 + tid] = g_cpb[r*NHH + h];
}

// ---------------- pool logits mma ----------------
__global__ __launch_bounds__(128) void pool_logits_mma()
{
    __shared__ __align__(128) char smem[24576];
    const uint32_t sb = smem_u32(smem);
    const int tid = threadIdx.x, w = tid >> 5, lane = tid & 31;
    const int bh = blockIdx.y, m0 = blockIdx.x * 128;
    const int h = bh & 7;
    const uint32_t A0 = 0, A1 = 8192, B0 = 16384, B1 = 20480;

    #pragma unroll
    for (int it = 0; it < 4; it++) {
        int idx = it*128 + tid, row = idx >> 2, ch = idx & 3;
        uint32_t so = (uint32_t)row*64 + (uint32_t)((ch ^ (row & 3))*16);
        const size_t src = ((size_t)bh*NTOK + m0 + row)*HDD + ch*8;
        cp_async16(sb + A0 + so, g_qshh + src);
        cp_async16(sb + A1 + so, g_qshl + src);
    }
    #pragma unroll
    for (int it = 0; it < 2; it++) {
        int idx = it*128 + tid, row = idx >> 2, ch = idx & 3;
        uint32_t so = (uint32_t)row*64 + (uint32_t)((ch ^ (row & 3))*16);
        const size_t src = ((size_t)bh*PP + row)*HDD + ch*8;
        cp_async16(sb + B0 + so, g_kph + src);
        cp_async16(sb + B1 + so, g_kpl + src);
    }
    CP_COMMIT(); CP_WAIT0();
    __syncthreads();

    float acc[2][8][4];
    #pragma unroll
    for (int i = 0; i < 2; i++)
        #pragma unroll
        for (int j = 0; j < 8; j++)
            #pragma unroll
            for (int e = 0; e < 4; e++) acc[i][j][e] = 0.f;

    #pragma unroll
    for (int pass = 0; pass < 3; pass++) {
        const uint32_t ab = sb + ((pass == 2) ? A1 : A0);
        const uint32_t bb = sb + ((pass == 1) ? B1 : B0);
        #pragma unroll
        for (int ks = 0; ks < 2; ks++) {
            uint32_t afr[2][4];
            #pragma unroll
            for (int tm = 0; tm < 2; tm++) {
                int row = w*32 + tm*16 + (lane & 15);
                int cc  = ks*2 + (lane >> 4);
                ldmx4(afr[tm], ab + (uint32_t)row*64 + (uint32_t)((cc ^ (row & 3))*16));
            }
            uint32_t bfr[4][4];
            #pragma unroll
            for (int tp = 0; tp < 4; tp++) {
                int g = lane >> 3;
                int row = tp*16 + ((g >> 1) & 1)*8 + (lane & 7);
                int cc  = ks*2 + (g & 1);
                ldmx4(bfr[tp], bb + (uint32_t)row*64 + (uint32_t)((cc ^ (row & 3))*16));
            }
            #pragma unroll
            for (int tm = 0; tm < 2; tm++)
                #pragma unroll
                for (int tn = 0; tn < 8; tn++)
                    mma16816(acc[tm][tn], afr[tm],
                             bfr[tn >> 1][(tn & 1)*2], bfr[tn >> 1][(tn & 1)*2 + 1]);
        }
    }

    #pragma unroll
    for (int tm = 0; tm < 2; tm++) {
        int gn = m0 + w*32 + tm*16 + (lane >> 2);
        #pragma unroll
        for (int tn = 0; tn < 8; tn++) {
            int p = tn*8 + 2*(lane & 3);
            float2 pb0 = *(const float2*)&g_pb[(size_t)gn*512 + h*64 + p];
            float2 pb1 = *(const float2*)&g_pb[(size_t)(gn+8)*512 + h*64 + p];
            *(float2*)&g_S[((size_t)bh*NTOK + gn)*PP + p] =
                make_float2(acc[tm][tn][0] + pb0.x, acc[tm][tn][1] + pb0.y);
            *(float2*)&g_S[((size_t)bh*NTOK + gn + 8)*PP + p] =
                make_float2(acc[tm][tn][2] + pb1.x, acc[tm][tn][3] + pb1.y);
        }
    }
}

// ---------------- attn6: local logits + joint softmax ----------------
__global__ __launch_bounds__(256) void attn_kernel6(const float* __restrict__ rpb_g)
{
    const int tid = threadIdx.x;
    const int bh = blockIdx.y, b = bh >> 3, h = bh & 7, chunk = blockIdx.x;
    const int w = tid >> 5, lane = tid & 31;
    const int tsub = lane >> 3, dg = lane & 7;

    float rpbl[LL];
    #pragma unroll
    for (int l = 0; l < LL; l++) rpbl[l] = rpb_g[h*LL + l];

    for (int s = 0; s < 8; s++) {
        const int n = chunk*256 + w*32 + s*4 + tsub;
        const int i = n >> 6, j = n & 63;

        const size_t qoff = ((size_t)bh*NTOK + n)*HDD + dg*4;
        uint2 uh = *(const uint2*)(g_qshh + qoff);
        uint2 ul = *(const uint2*)(g_qshl + qoff);
        float2 h01 = bf2f(uh.x), h23 = bf2f(uh.y);
        float2 l01 = bf2f(ul.x), l23 = bf2f(ul.y);
        float4 qv = make_float4(h01.x + l01.x, h01.y + l01.y,
                                h23.x + l23.x, h23.y + l23.y);

        float el[LL];
        bool  vlm[LL];
        #pragma unroll
        for (int l = 0; l < LL; l++) {
            int ii = i + l/3 - 1, jj = j + l%3 - 1;
            vlm[l] = ((unsigned)ii < 64u) && ((unsigned)jj < 64u);
            float sv = 0.f;
            if (vlm[l]) {
                float4 k4 = *(const float4*)(g_kn +
                    ((size_t)bh*NTOK + ii*64 + jj)*HDD + dg*4);
                sv = qv.x*k4.x + qv.y*k4.y + qv.z*k4.z + qv.w*k4.w;
            }
            el[l] = sv;
        }
        #pragma unroll
        for (int l = 0; l < LL; l++) {
            float sv = el[l];
            sv += __shfl_xor_sync(0xffffffffu, sv, 1);
            sv += __shfl_xor_sync(0xffffffffu, sv, 2);
            sv += __shfl_xor_sync(0xffffffffu, sv, 4);
            el[l] = vlm[l] ? (sv + rpbl[l]) : -1e30f;
        }

        const float* Sp = g_S + ((size_t)bh*NTOK + n)*PP + dg*8;
        float4 s03 = *(const float4*)Sp;
        float4 s47 = *(const float4*)(Sp + 4);
        float pl[8] = { s03.x, s03.y, s03.z, s03.w, s47.x, s47.y, s47.z, s47.w };

        float m = el[0];
        #pragma unroll
        for (int l = 1; l < LL; l++) m = fmaxf(m, el[l]);
        #pragma unroll
        for (int p = 0; p < 8; p++) m = fmaxf(m, pl[p]);
        m = fmaxf(m, __shfl_xor_sync(0xffffffffu, m, 1));
        m = fmaxf(m, __shfl_xor_sync(0xffffffffu, m, 2));
        m = fmaxf(m, __shfl_xor_sync(0xffffffffu, m, 4));

        float els = 0.f;
        #pragma unroll
        for (int l = 0; l < LL; l++) { el[l] = __expf(el[l] - m); els += el[l]; }
        float pes = 0.f;
        #pragma unroll
        for (int p = 0; p < 8; p++) { pl[p] = __expf(pl[p] - m); pes += pl[p]; }
        pes += __shfl_xor_sync(0xffffffffu, pes, 1);
        pes += __shfl_xor_sync(0xffffffffu, pes, 2);
        pes += __shfl_xor_sync(0xffffffffu, pes, 4);
        float inv = 1.f / (pes + els);

        {
            float wv[8], lv[8];
            #pragma unroll
            for (int p = 0; p < 8; p++) {
                wv[p] = pl[p] * inv;
                float hi = __bfloat162float(__float2bfloat16(wv[p]));
                lv[p] = wv[p] - hi;
            }
            uint4 xh4, xl4;
            xh4.x = pack_bf2(wv[0], wv[1]); xh4.y = pack_bf2(wv[2], wv[3]);
            xh4.z = pack_bf2(wv[4], wv[5]); xh4.w = pack_bf2(wv[6], wv[7]);
            xl4.x = pack_bf2(lv[0], lv[1]); xl4.y = pack_bf2(lv[2], lv[3]);
            xl4.z = pack_bf2(lv[4], lv[5]); xl4.w = pack_bf2(lv[6], lv[7]);
            size_t off = ((size_t)bh*NTOK + n)*PP + dg*8;
            *(uint4*)(g_apwh + off) = xh4;
            *(uint4*)(g_apwl + off) = xl4;
        }

        const float* altp = g_alt + ((size_t)(b*NTOK + n)*NHH + h)*12;
        float4 a03 = *(const float4*)altp;
        float4 a47 = *(const float4*)(altp + 4);
        float  a8  = altp[8];
        float av[LL] = { a03.x, a03.y, a03.z, a03.w, a47.x, a47.y, a47.z, a47.w, a8 };
        #pragma unroll
        for (int l = 0; l < LL; l++) av[l] += el[l]*inv;

        float4 xo = make_float4(0.f, 0.f, 0.f, 0.f);
        #pragma unroll
        for (int l = 0; l < LL; l++) {
            if (vlm[l]) {
                int ii = i + l/3 - 1, jj = j + l%3 - 1;
                float4 v4 = *(const float4*)(g_big +
                    (size_t)(b*NTOK + ii*64 + jj)*1024 + 512 + h*HDD + dg*4);
                xo.x = fmaf(av[l], v4.x, xo.x);
                xo.y = fmaf(av[l], v4.y, xo.y);
                xo.z = fmaf(av[l], v4.z, xo.z);
                xo.w = fmaf(av[l], v4.w, xo.w);
            }
        }
        *(float4*)(g_xloc + ((size_t)bh*NTOK + n)*HDD + dg*4) = xo;
    }
}

// ---------------- pool output mma ----------------
__global__ __launch_bounds__(128) void pool_out_mma()
{
    __shared__ __align__(128) char smem[40960];
    const uint32_t sb = smem_u32(smem);
    const int tid = threadIdx.x, w = tid >> 5, lane = tid & 31;
    const int bh = blockIdx.y, m0 = blockIdx.x * 128;
    const int b = bh >> 3, h = bh & 7;
    const uint32_t A0 = 0, A1 = 16384, B0 = 32768, B1 = 36864;

    #pragma unroll
    for (int it = 0; it < 8; it++) {
        int idx = it*128 + tid, row = idx >> 3, ch = idx & 7;
        uint32_t so = (uint32_t)row*128 + (uint32_t)((ch ^ (row & 7))*16);
        const size_t src = ((size_t)bh*NTOK + m0 + row)*PP + ch*8;
        cp_async16(sb + A0 + so, g_apwh + src);
        cp_async16(sb + A1 + so, g_apwl + src);
    }
    #pragma unroll
    for (int it = 0; it < 2; it++) {
        int idx = it*128 + tid, row = idx >> 3, ch = idx & 7;
        uint32_t so = (uint32_t)row*128 + (uint32_t)((ch ^ (row & 7))*16);
        const size_t src = ((size_t)bh*HDD + row)*PP + ch*8;
        cp_async16(sb + B0 + so, g_vth + src);
        cp_async16(sb + B1 + so, g_vtl + src);
    }
    CP_COMMIT(); CP_WAIT0();
    __syncthreads();

    float acc[2][4][4];
    #pragma unroll
    for (int i = 0; i < 2; i++)
        #pragma unroll
        for (int j = 0; j < 4; j++)
            #pragma unroll
            for (int e = 0; e < 4; e++) acc[i][j][e] = 0.f;

    #pragma unroll
    for (int pass = 0; pass < 3; pass++) {
        const uint32_t ab = sb + ((pass == 2) ? A1 : A0);
        const uint32_t bb = sb + ((pass == 1) ? B1 : B0);
        #pragma unroll
        for (int ks = 0; ks < 4; ks++) {
            uint32_t afr[2][4];
            #pragma unroll
            for (int tm = 0; tm < 2; tm++) {
                int row = w*32 + tm*16 + (lane & 15);
                int cc  = ks*2 + (lane >> 4);
                ldmx4(afr[tm], ab + (uint32_t)row*128 + (uint32_t)((cc ^ (row & 7))*16));
            }
            uint32_t bfr[2][4];
            #pragma unroll
            for (int tp = 0; tp < 2; tp++) {
                int g = lane >> 3;
                int row = tp*16 + ((g >> 1) & 1)*8 + (lane & 7);
                int cc  = ks*2 + (g & 1);
                ldmx4(bfr[tp], bb + (uint32_t)row*128 + (uint32_t)((cc ^ (row & 7))*16));
            }
            #pragma unroll
            for (int tm = 0; tm < 2; tm++)
                #pragma unroll
                for (int tn = 0; tn < 4; tn++)
                    mma16816(acc[tm][tn], afr[tm],
                             bfr[tn >> 1][(tn & 1)*2], bfr[tn >> 1][(tn & 1)*2 + 1]);
        }
    }

    #pragma unroll
    for (int tm = 0; tm < 2; tm++) {
        #pragma unroll
        for (int half = 0; half < 2; half++) {
            int gn = m0 + w*32 + tm*16 + (lane >> 2) + half*8;
            #pragma unroll
            for (int tn = 0; tn < 4; tn++) {
                int d = tn*8 + 2*(lane & 3);
                float2 x2 = *(const float2*)&g_xloc[((size_t)bh*NTOK + gn)*HDD + d];
                float r0 = acc[tm][tn][half*2 + 0] + x2.x;
                float r1 = acc[tm][tn][half*2 + 1] + x2.y;
                __nv_bfloat16 h0 = __float2bfloat16(r0), h1 = __float2bfloat16(r1);
                size_t off = (size_t)(b*NTOK + gn)*CC + h*HDD + d;
                *(uint32_t*)(g_ath + off) = pack_bf2(r0, r1);
                *(uint32_t*)(g_atl + off) = pack_bf2(r0 - __bfloat162float(h0),
                                                     r1 - __bfloat162float(h1));
            }
        }
    }
}

// ---------------- launch ----------------
extern "C" void kernel_launch(void* const* d_in, const int* in_sizes, int n_in,
                              void* d_out, int out_size)
{
    const float* x      = (const float*)d_in[0];
    const int*   rpi    = (const int*)  d_in[1];
    const float* table  = (const float*)d_in[2];
    const float* q_w    = (const float*)d_in[3];
    const float* q_b    = (const float*)d_in[4];
    const float* kv_w   = (const float*)d_in[5];
    const float* kv_b   = (const float*)d_in[6];
    const float* temp   = (const float*)d_in[7];
    const float* qe     = (const float*)d_in[8];
    const float* proj_w = (const float*)d_in[9];
    const float* proj_b = (const float*)d_in[10];
    const float* sr_w   = (const float*)d_in[11];
    const float* sr_b   = (const float*)d_in[12];
    const float* norm_g = (const float*)d_in[13];
    const float* norm_b = (const float*)d_in[14];
    const float* cpb1_w = (const float*)d_in[15];
    const float* cpb1_b = (const float*)d_in[16];
    const float* cpb2_w = (const float*)d_in[17];
    const float* cpb2_b = (const float*)d_in[18];
    const float* rpb    = (const float*)d_in[19];
    const float* lt     = (const float*)d_in[20];
    const float* lb     = (const float*)d_in[21];
    const float* sls    = (const float*)d_in[22];
    float* out = (float*)d_out;

    void *p_big, *p_xh, *p_xl, *p_ath, *p_atl, *p_wbh, *p_wbl, *p_pwh, *p_pwl, *p_bigb;
    cudaGetSymbolAddress(&p_big,  g_big);
    cudaGetSymbolAddress(&p_xh,   g_xh);  cudaGetSymbolAddress(&p_xl,  g_xl);
    cudaGetSymbolAddress(&p_ath,  g_ath); cudaGetSymbolAddress(&p_atl, g_atl);
    cudaGetSymbolAddress(&p_wbh,  g_wbh); cudaGetSymbolAddress(&p_wbl, g_wbl);
    cudaGetSymbolAddress(&p_pwh,  g_pwh); cudaGetSymbolAddress(&p_pwl, g_pwl);
    cudaGetSymbolAddress(&p_bigb, g_bigb);

    const int M = BB * NTOK;
    const int NX = M * CC;

    cudaFuncSetAttribute(gemm_mma, cudaFuncAttributeMaxDynamicSharedMemorySize, GS_TOT);

    #define BF(p) ((__nv_bfloat16*)(p))
    cvt_hilo<<<(NX+255)/256, 256>>>(x, BF(p_xh), BF(p_xl), NX);
    cvt_weights<<<(NW + NPJ + 1024 + 255)/256, 256>>>(q_w, kv_w, sr_w, proj_w,
                                                      q_b, kv_b, sr_b);
    cpb_kernel<<<TT/128, 128>>>(table, cpb1_w, cpb1_b, cpb2_w, cpb2_b);
    gemm_mma<<<dim3(8, M/128), 256, GS_TOT>>>(BF(p_xh), BF(p_xl), BF(p_wbh), BF(p_wbl),
                                              (float*)p_bigb, (float*)p_big, 1024, 2);

    normalize_kernel<<<M, CC>>>(qe, temp, sls);
    poolkv_kernel<<<BB*PP, 512>>>(norm_g, norm_b, kv_w, kv_b);
    pbias_kernel<<<NTOK, 512>>>(rpi);
    alt_kernel<<<(M*NHH)/256, 256>>>(lt, lb, qe, temp, sls);

    pool_logits_mma<<<dim3(NTOK/128, BB*NHH), 128>>>();
    attn_kernel6<<<dim3(16, BB*NHH), 256>>>(rpb);
    pool_out_mma<<<dim3(NTOK/128, BB*NHH), 128>>>();

    gemm_mma<<<dim3(2, M/128), 256, GS_TOT>>>(BF(p_ath), BF(p_atl), BF(p_pwh), BF(p_pwl),
                                              proj_b, out, CC, 0);
    #undef BF
}

// round 17
// speedup vs baseline: 1.1039x; 1.0583x over previous
#include <cuda_runtime.h>
#include <cuda_bf16.h>
#include <cstdint>

#define BB   4
#define NTOK 4096
#define CC   256
#define NHH  8
#define HDD  32
#define LL   9
#define PP   64
#define TT   4096

// ---------------- scratch ----------------
__device__ float g_big  [BB*NTOK*1024];    // [ - | - | v | xs ] (q,k segments unused)
__device__ float g_kn   [BB*NHH*NTOK*HDD]; // head-major [bh][n][d]
__device__ float g_cpb  [TT*NHH];
__device__ float g_pb   [NTOK*NHH*PP];     // [n][h][p]
__device__ float g_alt  [BB*NTOK*NHH*12];
__device__ float g_S    [BB*NHH*NTOK*PP];  // pool logits (+bias)
__device__ float g_xloc [BB*NHH*NTOK*HDD]; // local-path output

// bf16 operands
__device__ __nv_bfloat16 g_xh [BB*NTOK*CC], g_xl [BB*NTOK*CC];
__device__ __nv_bfloat16 g_ath[BB*NTOK*CC], g_atl[BB*NTOK*CC];
__device__ __nv_bfloat16 g_wbh[1024*CC],    g_wbl[1024*CC];
__device__ __nv_bfloat16 g_pwh[CC*CC],      g_pwl[CC*CC];
__device__ float         g_bigb[1024];
__device__ __nv_bfloat16 g_qshh[BB*NHH*NTOK*HDD], g_qshl[BB*NHH*NTOK*HDD]; // [bh][n][d]
__device__ __nv_bfloat16 g_kph [BB*NHH*PP*HDD],   g_kpl [BB*NHH*PP*HDD];
__device__ __nv_bfloat16 g_vth [BB*NHH*HDD*PP],   g_vtl [BB*NHH*HDD*PP];
__device__ __nv_bfloat16 g_apwh[BB*NHH*NTOK*PP],  g_apwl[BB*NHH*NTOK*PP];

// ---------------- helpers ----------------
__device__ __forceinline__ uint32_t smem_u32(const void* p) {
    uint32_t a;
    asm("{ .reg .u64 t; cvta.to.shared.u64 t, %1; cvt.u32.u64 %0, t; }" : "=r"(a) : "l"(p));
    return a;
}
__device__ __forceinline__ void cp_async16(uint32_t dst, const void* src) {
    asm volatile("cp.async.cg.shared.global [%0], [%1], 16;" :: "r"(dst), "l"(src) : "memory");
}
#define CP_COMMIT() asm volatile("cp.async.commit_group;" ::: "memory")
#define CP_WAIT0()  asm volatile("cp.async.wait_group 0;" ::: "memory")

__device__ __forceinline__ void ldmx4(uint32_t* r, uint32_t addr) {
    asm volatile("ldmatrix.sync.aligned.m8n8.x4.shared.b16 {%0,%1,%2,%3}, [%4];"
                 : "=r"(r[0]), "=r"(r[1]), "=r"(r[2]), "=r"(r[3]) : "r"(addr));
}
__device__ __forceinline__ void mma16816(float* c, const uint32_t* a, uint32_t b0, uint32_t b1) {
    asm volatile("mma.sync.aligned.m16n8k16.row.col.f32.bf16.bf16.f32 "
                 "{%0,%1,%2,%3}, {%4,%5,%6,%7}, {%8,%9}, {%0,%1,%2,%3};"
                 : "+f"(c[0]), "+f"(c[1]), "+f"(c[2]), "+f"(c[3])
                 : "r"(a[0]), "r"(a[1]), "r"(a[2]), "r"(a[3]), "r"(b0), "r"(b1));
}
__device__ __forceinline__ uint32_t pack_bf2(float a, float b) {
    __nv_bfloat162 t = __floats2bfloat162_rn(a, b);
    return *(uint32_t*)&t;
}
__device__ __forceinline__ float2 bf2f(uint32_t u) {
    __nv_bfloat162 t = *(__nv_bfloat162*)&u;
    return make_float2(__bfloat162float(t.x), __bfloat162float(t.y));
}

// ---------------- x hi/lo split ----------------
__global__ void cvt_hilo(const float* __restrict__ src,
                         __nv_bfloat16* __restrict__ hi,
                         __nv_bfloat16* __restrict__ lo, int n)
{
    int i = blockIdx.x * 256 + threadIdx.x;
    if (i < n) {
        float v = src[i];
        __nv_bfloat16 h = __float2bfloat16(v);
        hi[i] = h;
        lo[i] = __float2bfloat16(v - __bfloat162float(h));
    }
}

// ---------------- fused weight conversion ----------------
#define NW (1024*CC)
#define NPJ (CC*CC)
__global__ void cvt_weights(const float* __restrict__ qw, const float* __restrict__ kvw,
                            const float* __restrict__ srw, const float* __restrict__ pjw,
                            const float* __restrict__ qb, const float* __restrict__ kvb,
                            const float* __restrict__ srb)
{
    int idx = blockIdx.x * 256 + threadIdx.x;
    if (idx < NW) {
        int row = idx >> 8, col = idx & 255;
        float v = (row < 256) ? qw[row*256 + col]
                : (row < 768) ? kvw[(row-256)*256 + col]
                              : srw[(row-768)*256 + col];
        __nv_bfloat16 h = __float2bfloat16(v);
        g_wbh[idx] = h;
        g_wbl[idx] = __float2bfloat16(v - __bfloat162float(h));
    } else if (idx < NW + NPJ) {
        int j = idx - NW;
        float v = pjw[j];
        __nv_bfloat16 h = __float2bfloat16(v);
        g_pwh[j] = h;
        g_pwl[j] = __float2bfloat16(v - __bfloat162float(h));
    } else if (idx < NW + NPJ + 1024) {
        int j = idx - NW - NPJ;
        g_bigb[j] = (j < 256) ? qb[j] : (j < 768) ? kvb[j-256] : srb[j-768];
    }
}

// ---------------- HMMA GEMM with fused normalize epilogue ----------------
// act: 0 plain store; 3 fused q/k/v/xs routing (Nout==1024)
#define GS_A0   0
#define GS_A1   16384
#define GS_W0   32768
#define GS_W1   49152
#define GS_BIAS 65536
#define GS_QE   66048
#define GS_TOT  66560

__global__ __launch_bounds__(256) void gemm_mma(
    const __nv_bfloat16* __restrict__ Ah, const __nv_bfloat16* __restrict__ Al,
    const __nv_bfloat16* __restrict__ Wh, const __nv_bfloat16* __restrict__ Wl,
    const float* __restrict__ bias, float* __restrict__ Y, int Nout, int act,
    const float* __restrict__ qe, const float* __restrict__ temp,
    const float* __restrict__ sls)
{
    extern __shared__ __align__(128) char smem[];
    const uint32_t sb = smem_u32(smem);
    float* sbias = (float*)(smem + GS_BIAS);
    float* sqe   = (float*)(smem + GS_QE);

    const int tid = threadIdx.x, wid = tid >> 5, lane = tid & 31;
    const int n0 = blockIdx.x * 128, m0 = blockIdx.y * 128;
    const int warp_m = wid & 1, warp_n = wid >> 1;

    if (tid < 128) {
        sbias[tid] = bias[n0 + tid];
        sqe[tid] = (act == 3 && n0 < 256) ? qe[n0 + tid] : 0.f;
    }

    float acc[4][4][4];
    #pragma unroll
    for (int i = 0; i < 4; i++)
        #pragma unroll
        for (int j = 0; j < 4; j++)
            #pragma unroll
            for (int e = 0; e < 4; e++) acc[i][j][e] = 0.f;

    const int lrow0 = tid >> 3;
    const int luc   = tid & 7;

    auto issue = [&](int c, int buf) {
        int seg = c >> 2, ks0 = (c & 3) * 64;
        const __nv_bfloat16* Asrc = (seg < 2) ? Ah : Al;
        const __nv_bfloat16* Wsrc = (seg == 1) ? Wl : Wh;
        uint32_t ab = sb + (buf ? GS_A1 : GS_A0);
        uint32_t wb = sb + (buf ? GS_W1 : GS_W0);
        #pragma unroll
        for (int i = 0; i < 4; i++) {
            int row = lrow0 + i * 32;
            uint32_t soff = (uint32_t)row * 128 + (uint32_t)((luc ^ (row & 7)) * 16);
            cp_async16(ab + soff, Asrc + (size_t)(m0 + row) * CC + ks0 + luc * 8);
            cp_async16(wb + soff, Wsrc + (size_t)(n0 + row) * CC + ks0 + luc * 8);
        }
        CP_COMMIT();
    };

    issue(0, 0);

    for (int c = 0; c < 12; c++) {
        CP_WAIT0();
        __syncthreads();
        if (c + 1 < 12) issue(c + 1, (c + 1) & 1);

        const uint32_t ab = sb + ((c & 1) ? GS_A1 : GS_A0);
        const uint32_t wb = sb + ((c & 1) ? GS_W1 : GS_W0);

        #pragma unroll
        for (int ks = 0; ks < 4; ks++) {
            uint32_t afr[4][4];
            #pragma unroll
            for (int tm = 0; tm < 4; tm++) {
                int row = warp_m * 64 + tm * 16 + (lane & 15);
                int cc  = ks * 2 + (lane >> 4);
                ldmx4(afr[tm], ab + (uint32_t)row * 128 + (uint32_t)((cc ^ (row & 7)) * 16));
            }
            uint32_t bfr[2][4];
            #pragma unroll
            for (int tp = 0; tp < 2; tp++) {
                int g = lane >> 3;
                int row = warp_n * 32 + tp * 16 + ((g >> 1) & 1) * 8 + (lane & 7);
                int cc  = ks * 2 + (g & 1);
                ldmx4(bfr[tp], wb + (uint32_t)row * 128 + (uint32_t)((cc ^ (row & 7)) * 16));
            }
            #pragma unroll
            for (int tm = 0; tm < 4; tm++)
                #pragma unroll
                for (int tn = 0; tn < 4; tn++)
                    mma16816(acc[tm][tn], afr[tm],
                             bfr[tn >> 1][(tn & 1) * 2], bfr[tn >> 1][(tn & 1) * 2 + 1]);
        }
    }

    const int gc0 = n0 + warp_n * 32;          // warp-uniform segment base
    float sp_w = 0.f;
    if (act == 3 && gc0 < 256)
        sp_w = log1pf(expf(temp[(gc0 >> 5) & 7]));

    if (act == 0) {
        #pragma unroll
        for (int tm = 0; tm < 4; tm++) {
            int gr = m0 + warp_m * 64 + tm * 16 + (lane >> 2);
            #pragma unroll
            for (int tn = 0; tn < 4; tn++) {
                int lc = warp_n * 32 + tn * 8 + 2 * (lane & 3);
                int gc = n0 + lc;
                float b0 = sbias[lc], b1 = sbias[lc + 1];
                *(float2*)&Y[(size_t)gr * Nout + gc] =
                    make_float2(acc[tm][tn][0] + b0, acc[tm][tn][1] + b1);
                *(float2*)&Y[(size_t)(gr + 8) * Nout + gc] =
                    make_float2(acc[tm][tn][2] + b0, acc[tm][tn][3] + b1);
            }
        }
        return;
    }

    // act == 3: fused routing epilogue
    #pragma unroll
    for (int tm = 0; tm < 4; tm++) {
        #pragma unroll
        for (int half = 0; half < 2; half++) {
            const int gr = m0 + warp_m * 64 + tm * 16 + (lane >> 2) + half * 8;
            const int b = gr >> 12, n = gr & (NTOK - 1);
            float vals[8];
            #pragma unroll
            for (int tn = 0; tn < 4; tn++) {
                int lc = warp_n * 32 + tn * 8 + 2 * (lane & 3);
                vals[tn*2]   = acc[tm][tn][half*2]     + sbias[lc];
                vals[tn*2+1] = acc[tm][tn][half*2 + 1] + sbias[lc + 1];
            }
            if (gc0 < 512) {
                // q or k: per-head L2 norm (4-lane reduce over fragment owners)
                float ss = 0.f;
                #pragma unroll
                for (int i = 0; i < 8; i++) ss += vals[i]*vals[i];
                ss += __shfl_xor_sync(0xffffffffu, ss, 1);
                ss += __shfl_xor_sync(0xffffffffu, ss, 2);
                float inv = 1.f / fmaxf(sqrtf(ss), 1e-12f);
                const int h = (gc0 >> 5) & 7;
                const size_t hm = (((size_t)(b*NHH + h))*NTOK + n)*HDD;
                if (gc0 < 256) {
                    float sc = sp_w * sls[n];
                    #pragma unroll
                    for (int tn = 0; tn < 4; tn++) {
                        int d = tn*8 + 2*(lane & 3);
                        int lc = warp_n*32 + d;
                        float q0 = (vals[tn*2]*inv   + sqe[lc])   * sc;
                        float q1 = (vals[tn*2+1]*inv + sqe[lc+1]) * sc;
                        __nv_bfloat16 h0 = __float2bfloat16(q0);
                        __nv_bfloat16 h1 = __float2bfloat16(q1);
                        *(uint32_t*)(g_qshh + hm + d) = pack_bf2(q0, q1);
                        *(uint32_t*)(g_qshl + hm + d) =
                            pack_bf2(q0 - __bfloat162float(h0), q1 - __bfloat162float(h1));
                    }
                } else {
                    #pragma unroll
                    for (int tn = 0; tn < 4; tn++) {
                        int d = tn*8 + 2*(lane & 3);
                        *(float2*)(g_kn + hm + d) =
                            make_float2(vals[tn*2]*inv, vals[tn*2+1]*inv);
                    }
                }
            } else {
                const bool do_gelu = (gc0 >= 768);
                #pragma unroll
                for (int tn = 0; tn < 4; tn++) {
                    int lc = warp_n*32 + tn*8 + 2*(lane & 3);
                    float r0 = vals[tn*2], r1 = vals[tn*2+1];
                    if (do_gelu) { r0 *= normcdff(r0); r1 *= normcdff(r1); }
                    *(float2*)&Y[(size_t)gr * Nout + n0 + lc] = make_float2(r0, r1);
                }
            }
        }
    }
}

// ---------------- learnable-token precompute ----------------
__global__ void alt_kernel(const float* __restrict__ lt_g, const float* __restrict__ lb_g,
                           const float* __restrict__ qe, const float* __restrict__ temp,
                           const float* __restrict__ sls)
{
    __shared__ float lts[NHH*HDD*LL];
    __shared__ float lbs[NHH*LL];
    __shared__ float qelt[NHH*LL];
    __shared__ float sp[NHH];
    int tid = threadIdx.x;
    for (int i = tid; i < NHH*HDD*LL; i += 256) lts[i] = lt_g[i];
    if (tid < NHH*LL) lbs[tid] = lb_g[tid];
    if (tid < NHH) sp[tid] = log1pf(expf(temp[tid]));
    __syncthreads();
    if (tid < NHH*LL) {
        int h = tid / LL, l = tid % LL;
        float s = 0.f;
        for (int d = 0; d < HDD; d++)
            s += qe[h*HDD + d] * lts[(h*HDD + d)*LL + l];
        qelt[tid] = s;
    }
    __syncthreads();

    int idx = blockIdx.x * 256 + tid;
    int bn = idx >> 3, h = idx & 7;
    int b = bn >> 12, n = bn & (NTOK - 1);

    const size_t qoff = ((size_t)(b*NHH + h)*NTOK + n)*HDD;
    const __nv_bfloat16* qh = g_qshh + qoff;
    const __nv_bfloat16* ql = g_qshl + qoff;

    float invs = 1.f / (sp[h] * sls[n]);
    float acc[LL];
    #pragma unroll
    for (int l = 0; l < LL; l++) acc[l] = 0.f;
    #pragma unroll 4
    for (int d = 0; d < HDD; d++) {
        float q = __bfloat162float(qh[d]) + __bfloat162float(ql[d]);
        #pragma unroll
        for (int l = 0; l < LL; l++)
            acc[l] = fmaf(q, lts[(h*HDD + d)*LL + l], acc[l]);
    }
    float* outp = g_alt + (size_t)idx * 12;
    #pragma unroll
    for (int l = 0; l < LL; l++)
        outp[l] = acc[l] * invs - qelt[h*LL + l] + lbs[h*LL + l];
    outp[9] = 0.f; outp[10] = 0.f; outp[11] = 0.f;
}

// ---------------- fused pool+LN+kv projection ----------------
__global__ __launch_bounds__(512) void poolkv_kernel(
    const float* __restrict__ ng, const float* __restrict__ nb,
    const float* __restrict__ kv_w, const float* __restrict__ kv_b)
{
    __shared__ float psum[512];
    __shared__ __align__(16) float xr[CC];
    __shared__ float s1[8], s2[8];

    int bp = blockIdx.x; int b = bp >> 6, p = bp & 63;
    int ph = p >> 3, pw = p & 7;
    int tid = threadIdx.x;
    int c = tid & 255, half = tid >> 8;

    float s = 0.f;
    #pragma unroll
    for (int r = 0; r < 4; r++)
        #pragma unroll
        for (int q = 0; q < 8; q++) {
            int n = (ph*8 + half*4 + r) * 64 + pw*8 + q;
            s += g_big[(size_t)(b*NTOK + n)*1024 + 768 + c];
        }
    psum[tid] = s;
    __syncthreads();

    if (tid < 256) {
        float avg = (psum[c] + psum[c + 256]) * (1.f/64.f);
        float v1 = avg, v2 = avg*avg;
        #pragma unroll
        for (int o = 16; o; o >>= 1) {
            v1 += __shfl_xor_sync(0xffffffffu, v1, o);
            v2 += __shfl_xor_sync(0xffffffffu, v2, o);
        }
        int w = tid >> 5, lane = tid & 31;
        if (lane == 0) { s1[w] = v1; s2[w] = v2; }
        psum[tid] = avg;
    }
    __syncthreads();
    if (tid < 256) {
        float m1 = 0.f, m2 = 0.f;
        #pragma unroll
        for (int ww = 0; ww < 8; ww++) { m1 += s1[ww]; m2 += s2[ww]; }
        m1 *= (1.f/256.f); m2 *= (1.f/256.f);
        float var = m2 - m1*m1;
        xr[tid] = (psum[tid] - m1) * rsqrtf(var + 1e-5f) * ng[tid] + nb[tid];
    }
    __syncthreads();

    int o = tid;
    float acc = kv_b[o];
    const float4* w4 = (const float4*)(kv_w + (size_t)o * CC);
    const float4* x4 = (const float4*)xr;
    #pragma unroll 8
    for (int k = 0; k < 64; k++) {
        float4 w = w4[k], xv = x4[k];
        acc += w.x*xv.x + w.y*xv.y + w.z*xv.z + w.w*xv.w;
    }
    int lane = tid & 31;
    if (o < CC) {
        float sv = acc*acc;
        #pragma unroll
        for (int q = 16; q; q >>= 1) sv += __shfl_xor_sync(0xffffffffu, sv, q);
        float kn = acc / fmaxf(sqrtf(sv), 1e-12f);
        int h = o >> 5;
        size_t idx = ((size_t)(b*NHH + h)*PP + p)*HDD + lane;
        __nv_bfloat16 kh = __float2bfloat16(kn);
        g_kph[idx] = kh;
        g_kpl[idx] = __float2bfloat16(kn - __bfloat162float(kh));
    } else {
        int oo = o - CC; int h = oo >> 5, d = oo & 31;
        size_t idx = ((size_t)(b*NHH + h)*HDD + d)*PP + p;
        __nv_bfloat16 vh = __float2bfloat16(acc);
        g_vth[idx] = vh;
        g_vtl[idx] = __float2bfloat16(acc - __bfloat162float(vh));
    }
}

// ---------------- CPB MLP ----------------
__global__ void cpb_kernel(const float* __restrict__ table,
                           const float* __restrict__ w1, const float* __restrict__ b1,
                           const float* __restrict__ w2, const float* __restrict__ b2)
{
    __shared__ float sw1[1024], sb1[512], sw2[4096];
    int tid = threadIdx.x;
    for (int i = tid; i < 1024; i += 128) sw1[i] = w1[i];
    for (int i = tid; i <  512; i += 128) sb1[i] = b1[i];
    for (int i = tid; i < 4096; i += 128) sw2[i] = w2[i];
    __syncthreads();

    int t = blockIdx.x * 128 + tid;
    float c0 = table[2*t], c1 = table[2*t+1];
    float acc[NHH];
    #pragma unroll
    for (int h = 0; h < NHH; h++) acc[h] = b2[h];
    for (int j = 0; j < 512; j++) {
        float hj = fmaxf(fmaf(c0, sw1[2*j], fmaf(c1, sw1[2*j+1], sb1[j])), 0.f);
        #pragma unroll
        for (int h = 0; h < NHH; h++) acc[h] = fmaf(hj, sw2[h*512 + j], acc[h]);
    }
    #pragma unroll
    for (int h = 0; h < NHH; h++) g_cpb[t*NHH + h] = acc[h];
}

// ---------------- pool bias gather ----------------
__global__ void pbias_kernel(const int* __restrict__ rpi)
{
    int n = blockIdx.x, tid = threadIdx.x;
    int h = tid >> 6, p = tid & 63;
    int r = rpi[n*PP + p];
    g_pb[(size_t)n*512 + tid] = g_cpb[r*NHH + h];
}

// ---------------- pool logits mma ----------------
__global__ __launch_bounds__(128) void pool_logits_mma()
{
    __shared__ __align__(128) char smem[24576];
    const uint32_t sb = smem_u32(smem);
    const int tid = threadIdx.x, w = tid >> 5, lane = tid & 31;
    const int bh = blockIdx.y, m0 = blockIdx.x * 128;
    const int h = bh & 7;
    const uint32_t A0 = 0, A1 = 8192, B0 = 16384, B1 = 20480;

    #pragma unroll
    for (int it = 0; it < 4; it++) {
        int idx = it*128 + tid, row = idx >> 2, ch = idx & 3;
        uint32_t so = (uint32_t)row*64 + (uint32_t)((ch ^ (row & 3))*16);
        const size_t src = ((size_t)bh*NTOK + m0 + row)*HDD + ch*8;
        cp_async16(sb + A0 + so, g_qshh + src);
        cp_async16(sb + A1 + so, g_qshl + src);
    }
    #pragma unroll
    for (int it = 0; it < 2; it++) {
        int idx = it*128 + tid, row = idx >> 2, ch = idx & 3;
        uint32_t so = (uint32_t)row*64 + (uint32_t)((ch ^ (row & 3))*16);
        const size_t src = ((size_t)bh*PP + row)*HDD + ch*8;
        cp_async16(sb + B0 + so, g_kph + src);
        cp_async16(sb + B1 + so, g_kpl + src);
    }
    CP_COMMIT(); CP_WAIT0();
    __syncthreads();

    float acc[2][8][4];
    #pragma unroll
    for (int i = 0; i < 2; i++)
        #pragma unroll
        for (int j = 0; j < 8; j++)
            #pragma unroll
            for (int e = 0; e < 4; e++) acc[i][j][e] = 0.f;

    #pragma unroll
    for (int pass = 0; pass < 3; pass++) {
        const uint32_t ab = sb + ((pass == 2) ? A1 : A0);
        const uint32_t bb = sb + ((pass == 1) ? B1 : B0);
        #pragma unroll
        for (int ks = 0; ks < 2; ks++) {
            uint32_t afr[2][4];
            #pragma unroll
            for (int tm = 0; tm < 2; tm++) {
                int row = w*32 + tm*16 + (lane & 15);
                int cc  = ks*2 + (lane >> 4);
                ldmx4(afr[tm], ab + (uint32_t)row*64 + (uint32_t)((cc ^ (row & 3))*16));
            }
            uint32_t bfr[4][4];
            #pragma unroll
            for (int tp = 0; tp < 4; tp++) {
                int g = lane >> 3;
                int row = tp*16 + ((g >> 1) & 1)*8 + (lane & 7);
                int cc  = ks*2 + (g & 1);
                ldmx4(bfr[tp], bb + (uint32_t)row*64 + (uint32_t)((cc ^ (row & 3))*16));
            }
            #pragma unroll
            for (int tm = 0; tm < 2; tm++)
                #pragma unroll
                for (int tn = 0; tn < 8; tn++)
                    mma16816(acc[tm][tn], afr[tm],
                             bfr[tn >> 1][(tn & 1)*2], bfr[tn >> 1][(tn & 1)*2 + 1]);
        }
    }

    #pragma unroll
    for (int tm = 0; tm < 2; tm++) {
        int gn = m0 + w*32 + tm*16 + (lane >> 2);
        #pragma unroll
        for (int tn = 0; tn < 8; tn++) {
            int p = tn*8 + 2*(lane & 3);
            float2 pb0 = *(const float2*)&g_pb[(size_t)gn*512 + h*64 + p];
            float2 pb1 = *(const float2*)&g_pb[(size_t)(gn+8)*512 + h*64 + p];
            *(float2*)&g_S[((size_t)bh*NTOK + gn)*PP + p] =
                make_float2(acc[tm][tn][0] + pb0.x, acc[tm][tn][1] + pb0.y);
            *(float2*)&g_S[((size_t)bh*NTOK + gn + 8)*PP + p] =
                make_float2(acc[tm][tn][2] + pb1.x, acc[tm][tn][3] + pb1.y);
        }
    }
}

// ---------------- attn6: local logits + joint softmax ----------------
__global__ __launch_bounds__(256) void attn_kernel6(const float* __restrict__ rpb_g)
{
    const int tid = threadIdx.x;
    const int bh = blockIdx.y, b = bh >> 3, h = bh & 7, chunk = blockIdx.x;
    const int w = tid >> 5, lane = tid & 31;
    const int tsub = lane >> 3, dg = lane & 7;

    float rpbl[LL];
    #pragma unroll
    for (int l = 0; l < LL; l++) rpbl[l] = rpb_g[h*LL + l];

    for (int s = 0; s < 8; s++) {
        const int n = chunk*256 + w*32 + s*4 + tsub;
        const int i = n >> 6, j = n & 63;

        const size_t qoff = ((size_t)bh*NTOK + n)*HDD + dg*4;
        uint2 uh = *(const uint2*)(g_qshh + qoff);
        uint2 ul = *(const uint2*)(g_qshl + qoff);
        float2 h01 = bf2f(uh.x), h23 = bf2f(uh.y);
        float2 l01 = bf2f(ul.x), l23 = bf2f(ul.y);
        float4 qv = make_float4(h01.x + l01.x, h01.y + l01.y,
                                h23.x + l23.x, h23.y + l23.y);

        float el[LL];
        bool  vlm[LL];
        #pragma unroll
        for (int l = 0; l < LL; l++) {
            int ii = i + l/3 - 1, jj = j + l%3 - 1;
            vlm[l] = ((unsigned)ii < 64u) && ((unsigned)jj < 64u);
            float sv = 0.f;
            if (vlm[l]) {
                float4 k4 = *(const float4*)(g_kn +
                    ((size_t)bh*NTOK + ii*64 + jj)*HDD + dg*4);
                sv = qv.x*k4.x + qv.y*k4.y + qv.z*k4.z + qv.w*k4.w;
            }
            el[l] = sv;
        }
        #pragma unroll
        for (int l = 0; l < LL; l++) {
            float sv = el[l];
            sv += __shfl_xor_sync(0xffffffffu, sv, 1);
            sv += __shfl_xor_sync(0xffffffffu, sv, 2);
            sv += __shfl_xor_sync(0xffffffffu, sv, 4);
            el[l] = vlm[l] ? (sv + rpbl[l]) : -1e30f;
        }

        const float* Sp = g_S + ((size_t)bh*NTOK + n)*PP + dg*8;
        float4 s03 = *(const float4*)Sp;
        float4 s47 = *(const float4*)(Sp + 4);
        float pl[8] = { s03.x, s03.y, s03.z, s03.w, s47.x, s47.y, s47.z, s47.w };

        float m = el[0];
        #pragma unroll
        for (int l = 1; l < LL; l++) m = fmaxf(m, el[l]);
        #pragma unroll
        for (int p = 0; p < 8; p++) m = fmaxf(m, pl[p]);
        m = fmaxf(m, __shfl_xor_sync(0xffffffffu, m, 1));
        m = fmaxf(m, __shfl_xor_sync(0xffffffffu, m, 2));
        m = fmaxf(m, __shfl_xor_sync(0xffffffffu, m, 4));

        float els = 0.f;
        #pragma unroll
        for (int l = 0; l < LL; l++) { el[l] = __expf(el[l] - m); els += el[l]; }
        float pes = 0.f;
        #pragma unroll
        for (int p = 0; p < 8; p++) { pl[p] = __expf(pl[p] - m); pes += pl[p]; }
        pes += __shfl_xor_sync(0xffffffffu, pes, 1);
        pes += __shfl_xor_sync(0xffffffffu, pes, 2);
        pes += __shfl_xor_sync(0xffffffffu, pes, 4);
        float inv = 1.f / (pes + els);

        {
            float wv[8], lv[8];
            #pragma unroll
            for (int p = 0; p < 8; p++) {
                wv[p] = pl[p] * inv;
                float hi = __bfloat162float(__float2bfloat16(wv[p]));
                lv[p] = wv[p] - hi;
            }
            uint4 xh4, xl4;
            xh4.x = pack_bf2(wv[0], wv[1]); xh4.y = pack_bf2(wv[2], wv[3]);
            xh4.z = pack_bf2(wv[4], wv[5]); xh4.w = pack_bf2(wv[6], wv[7]);
            xl4.x = pack_bf2(lv[0], lv[1]); xl4.y = pack_bf2(lv[2], lv[3]);
            xl4.z = pack_bf2(lv[4], lv[5]); xl4.w = pack_bf2(lv[6], lv[7]);
            size_t off = ((size_t)bh*NTOK + n)*PP + dg*8;
            *(uint4*)(g_apwh + off) = xh4;
            *(uint4*)(g_apwl + off) = xl4;
        }

        const float* altp = g_alt + ((size_t)(b*NTOK + n)*NHH + h)*12;
        float4 a03 = *(const float4*)altp;
        float4 a47 = *(const float4*)(altp + 4);
        float  a8  = altp[8];
        float av[LL] = { a03.x, a03.y, a03.z, a03.w, a47.x, a47.y, a47.z, a47.w, a8 };
        #pragma unroll
        for (int l = 0; l < LL; l++) av[l] += el[l]*inv;

        float4 xo = make_float4(0.f, 0.f, 0.f, 0.f);
        #pragma unroll
        for (int l = 0; l < LL; l++) {
            if (vlm[l]) {
                int ii = i + l/3 - 1, jj = j + l%3 - 1;
                float4 v4 = *(const float4*)(g_big +
                    (size_t)(b*NTOK + ii*64 + jj)*1024 + 512 + h*HDD + dg*4);
                xo.x = fmaf(av[l], v4.x, xo.x);
                xo.y = fmaf(av[l], v4.y, xo.y);
                xo.z = fmaf(av[l], v4.z, xo.z);
                xo.w = fmaf(av[l], v4.w, xo.w);
            }
        }
        *(float4*)(g_xloc + ((size_t)bh*NTOK + n)*HDD + dg*4) = xo;
    }
}

// ---------------- pool output mma ----------------
__global__ __launch_bounds__(128) void pool_out_mma()
{
    __shared__ __align__(128) char smem[40960];
    const uint32_t sb = smem_u32(smem);
    const int tid = threadIdx.x, w = tid >> 5, lane = tid & 31;
    const int bh = blockIdx.y, m0 = blockIdx.x * 128;
    const int b = bh >> 3, h = bh & 7;
    const uint32_t A0 = 0, A1 = 16384, B0 = 32768, B1 = 36864;

    #pragma unroll
    for (int it = 0; it < 8; it++) {
        int idx = it*128 + tid, row = idx >> 3, ch = idx & 7;
        uint32_t so = (uint32_t)row*128 + (uint32_t)((ch ^ (row & 7))*16);
        const size_t src = ((size_t)bh*NTOK + m0 + row)*PP + ch*8;
        cp_async16(sb + A0 + so, g_apwh + src);
        cp_async16(sb + A1 + so, g_apwl + src);
    }
    #pragma unroll
    for (int it = 0; it < 2; it++) {
        int idx = it*128 + tid, row = idx >> 3, ch = idx & 7;
        uint32_t so = (uint32_t)row*128 + (uint32_t)((ch ^ (row & 7))*16);
        const size_t src = ((size_t)bh*HDD + row)*PP + ch*8;
        cp_async16(sb + B0 + so, g_vth + src);
        cp_async16(sb + B1 + so, g_vtl + src);
    }
    CP_COMMIT(); CP_WAIT0();
    __syncthreads();

    float acc[2][4][4];
    #pragma unroll
    for (int i = 0; i < 2; i++)
        #pragma unroll
        for (int j = 0; j < 4; j++)
            #pragma unroll
            for (int e = 0; e < 4; e++) acc[i][j][e] = 0.f;

    #pragma unroll
    for (int pass = 0; pass < 3; pass++) {
        const uint32_t ab = sb + ((pass == 2) ? A1 : A0);
        const uint32_t bb = sb + ((pass == 1) ? B1 : B0);
        #pragma unroll
        for (int ks = 0; ks < 4; ks++) {
            uint32_t afr[2][4];
            #pragma unroll
            for (int tm = 0; tm < 2; tm++) {
                int row = w*32 + tm*16 + (lane & 15);
                int cc  = ks*2 + (lane >> 4);
                ldmx4(afr[tm], ab + (uint32_t)row*128 + (uint32_t)((cc ^ (row & 7))*16));
            }
            uint32_t bfr[2][4];
            #pragma unroll
            for (int tp = 0; tp < 2; tp++) {
                int g = lane >> 3;
                int row = tp*16 + ((g >> 1) & 1)*8 + (lane & 7);
                int cc  = ks*2 + (g & 1);
                ldmx4(bfr[tp], bb + (uint32_t)row*128 + (uint32_t)((cc ^ (row & 7))*16));
            }
            #pragma unroll
            for (int tm = 0; tm < 2; tm++)
                #pragma unroll
                for (int tn = 0; tn < 4; tn++)
                    mma16816(acc[tm][tn], afr[tm],
                             bfr[tn >> 1][(tn & 1)*2], bfr[tn >> 1][(tn & 1)*2 + 1]);
        }
    }

    #pragma unroll
    for (int tm = 0; tm < 2; tm++) {
        #pragma unroll
        for (int half = 0; half < 2; half++) {
            int gn = m0 + w*32 + tm*16 + (lane >> 2) + half*8;
            #pragma unroll
            for (int tn = 0; tn < 4; tn++) {
                int d = tn*8 + 2*(lane & 3);
                float2 x2 = *(const float2*)&g_xloc[((size_t)bh*NTOK + gn)*HDD + d];
                float r0 = acc[tm][tn][half*2 + 0] + x2.x;
                float r1 = acc[tm][tn][half*2 + 1] + x2.y;
                __nv_bfloat16 h0 = __float2bfloat16(r0), h1 = __float2bfloat16(r1);
                size_t off = (size_t)(b*NTOK + gn)*CC + h*HDD + d;
                *(uint32_t*)(g_ath + off) = pack_bf2(r0, r1);
                *(uint32_t*)(g_atl + off) = pack_bf2(r0 - __bfloat162float(h0),
                                                     r1 - __bfloat162float(h1));
            }
        }
    }
}

// ---------------- launch ----------------
extern "C" void kernel_launch(void* const* d_in, const int* in_sizes, int n_in,
                              void* d_out, int out_size)
{
    const float* x      = (const float*)d_in[0];
    const int*   rpi    = (const int*)  d_in[1];
    const float* table  = (const float*)d_in[2];
    const float* q_w    = (const float*)d_in[3];
    const float* q_b    = (const float*)d_in[4];
    const float* kv_w   = (const float*)d_in[5];
    const float* kv_b   = (const float*)d_in[6];
    const float* temp   = (const float*)d_in[7];
    const float* qe     = (const float*)d_in[8];
    const float* proj_w = (const float*)d_in[9];
    const float* proj_b = (const float*)d_in[10];
    const float* sr_w   = (const float*)d_in[11];
    const float* sr_b   = (const float*)d_in[12];
    const float* norm_g = (const float*)d_in[13];
    const float* norm_b = (const float*)d_in[14];
    const float* cpb1_w = (const float*)d_in[15];
    const float* cpb1_b = (const float*)d_in[16];
    const float* cpb2_w = (const float*)d_in[17];
    const float* cpb2_b = (const float*)d_in[18];
    const float* rpb    = (const float*)d_in[19];
    const float* lt     = (const float*)d_in[20];
    const float* lb     = (const float*)d_in[21];
    const float* sls    = (const float*)d_in[22];
    float* out = (float*)d_out;

    void *p_big, *p_xh, *p_xl, *p_ath, *p_atl, *p_wbh, *p_wbl, *p_pwh, *p_pwl, *p_bigb;
    cudaGetSymbolAddress(&p_big,  g_big);
    cudaGetSymbolAddress(&p_xh,   g_xh);  cudaGetSymbolAddress(&p_xl,  g_xl);
    cudaGetSymbolAddress(&p_ath,  g_ath); cudaGetSymbolAddress(&p_atl, g_atl);
    cudaGetSymbolAddress(&p_wbh,  g_wbh); cudaGetSymbolAddress(&p_wbl, g_wbl);
    cudaGetSymbolAddress(&p_pwh,  g_pwh); cudaGetSymbolAddress(&p_pwl, g_pwl);
    cudaGetSymbolAddress(&p_bigb, g_bigb);

    const int M = BB * NTOK;
    const int NX = M * CC;

    cudaFuncSetAttribute(gemm_mma, cudaFuncAttributeMaxDynamicSharedMemorySize, GS_TOT);

    #define BF(p) ((__nv_bfloat16*)(p))
    cvt_hilo<<<(NX+255)/256, 256>>>(x, BF(p_xh), BF(p_xl), NX);
    cvt_weights<<<(NW + NPJ + 1024 + 255)/256, 256>>>(q_w, kv_w, sr_w, proj_w,
                                                      q_b, kv_b, sr_b);
    cpb_kernel<<<TT/128, 128>>>(table, cpb1_w, cpb1_b, cpb2_w, cpb2_b);
    // big fused GEMM with normalize-in-epilogue (act=3)
    gemm_mma<<<dim3(8, M/128), 256, GS_TOT>>>(BF(p_xh), BF(p_xl), BF(p_wbh), BF(p_wbl),
                                              (float*)p_bigb, (float*)p_big, 1024, 3,
                                              qe, temp, sls);

    poolkv_kernel<<<BB*PP, 512>>>(norm_g, norm_b, kv_w, kv_b);
    pbias_kernel<<<NTOK, 512>>>(rpi);
    alt_kernel<<<(M*NHH)/256, 256>>>(lt, lb, qe, temp, sls);

    pool_logits_mma<<<dim3(NTOK/128, BB*NHH), 128>>>();
    attn_kernel6<<<dim3(16, BB*NHH), 256>>>(rpb);
    pool_out_mma<<<dim3(NTOK/128, BB*NHH), 128>>>();

    gemm_mma<<<dim3(2, M/128), 256, GS_TOT>>>(BF(p_ath), BF(p_atl), BF(p_pwh), BF(p_pwl),
                                              proj_b, out, CC, 0, nullptr, nullptr, nullptr);
    #undef BF
}